// round 9
// baseline (speedup 1.0000x reference)
#include <cuda_runtime.h>
#include <cuda_bf16.h>

#define BB 64      // batch
#define SS 512     // seq len
#define DD 768     // input dim
#define HH 512     // hidden
#define TT 21      // tags
#define G4 2048    // 4*H
#define H2 1024    // 2*H

// ---------------- scratch (device globals; no allocation allowed) ------------
__device__ float g_pre[(size_t)2 * SS * BB * G4];   // [dir][s][b][4H]
__device__ float g_h[(size_t)SS * BB * H2];          // [s][b][2H] (fwd | bwd)
__device__ float g_c[(size_t)2 * BB * HH];           // [dir][b][H]
__device__ float g_emis[(size_t)SS * BB * TT];       // [s][b][T]
__device__ unsigned char g_hist[(size_t)BB * SS * TT]; // viterbi backtrace

// =============================================================================
// 1) NAIVE pre-projection: one thread per (dir, s, b, n).
//    pre = x[b][s][:] . Wih[n][:] + bias[n]
// =============================================================================
__global__ __launch_bounds__(256) void k_pre_naive(
    const float* __restrict__ x,
    const float* __restrict__ Wf, const float* __restrict__ bf,
    const float* __restrict__ Wb, const float* __restrict__ bb)
{
    long long idx = (long long)blockIdx.x * 256 + threadIdx.x;
    const int n   = (int)(idx & 2047);
    long long r   = idx >> 11;
    const int b   = (int)(r & 63);  r >>= 6;
    const int s   = (int)(r & 511);
    const int dir = (int)(r >> 9);

    const float* __restrict__ W    = dir ? Wb : Wf;
    const float* __restrict__ bias = dir ? bb : bf;
    const float* xr = x + ((size_t)b * SS + s) * DD;
    const float* wr = W + (size_t)n * DD;

    float acc = bias[n];
#pragma unroll 8
    for (int k = 0; k < DD; k++) acc += xr[k] * wr[k];

    g_pre[(((size_t)dir * SS + s) * BB + b) * G4 + n] = acc;
}

// =============================================================================
// 2) NAIVE fused LSTM step (one launch per t): one thread per (dir, b, j).
// =============================================================================
__global__ __launch_bounds__(256) void k_step_naive(
    int t, const float* __restrict__ Whf, const float* __restrict__ Whb)
{
    const int idx = blockIdx.x * 256 + threadIdx.x;   // 0..65535
    const int j   = idx & 511;
    const int b   = (idx >> 9) & 63;
    const int dir = idx >> 15;
    const int tpos = dir ? (SS - 1 - t) : t;

    const float* __restrict__ pre =
        g_pre + (((size_t)dir * SS + tpos) * BB + b) * G4;
    float gi = pre[j];
    float gf = pre[HH + j];
    float gg = pre[2 * HH + j];
    float go = pre[3 * HH + j];

    float cp = 0.f;
    if (t > 0) {
        const int tprev = dir ? (tpos + 1) : (tpos - 1);
        const float* __restrict__ hp =
            g_h + ((size_t)tprev * BB + b) * H2 + dir * HH;
        const float* __restrict__ W = dir ? Whb : Whf;
        const float* w0 = W + (size_t)(0 * HH + j) * HH;
        const float* w1 = W + (size_t)(1 * HH + j) * HH;
        const float* w2 = W + (size_t)(2 * HH + j) * HH;
        const float* w3 = W + (size_t)(3 * HH + j) * HH;
#pragma unroll 4
        for (int k = 0; k < HH; k++) {
            float hv = hp[k];
            gi += w0[k] * hv;
            gf += w1[k] * hv;
            gg += w2[k] * hv;
            go += w3[k] * hv;
        }
        cp = g_c[((size_t)dir * BB + b) * HH + j];
    }

    float iv = 1.f / (1.f + expf(-gi));
    float fv = 1.f / (1.f + expf(-gf));
    float gv = tanhf(gg);
    float ov = 1.f / (1.f + expf(-go));
    float cn = fv * cp + iv * gv;
    g_c[((size_t)dir * BB + b) * HH + j] = cn;
    g_h[((size_t)tpos * BB + b) * H2 + dir * HH + j] = ov * tanhf(cn);
}

// =============================================================================
// 3) NAIVE emissions: one thread per (s, b, n).
// =============================================================================
__global__ __launch_bounds__(256) void k_emis_naive(
    const float* __restrict__ Wout, const float* __restrict__ bout)
{
    const int idx = blockIdx.x * 256 + threadIdx.x;
    if (idx >= SS * BB * TT) return;
    const int n = idx % TT;
    const int r = idx / TT;
    const int b = r & 63;
    const int s = r >> 6;

    const float* __restrict__ hr = g_h + ((size_t)s * BB + b) * H2;
    const float* __restrict__ wr = Wout + (size_t)n * H2;
    float acc = bout[n];
#pragma unroll 8
    for (int k = 0; k < H2; k++) acc += hr[k] * wr[k];
    g_emis[((size_t)s * BB + b) * TT + n] = acc;
}

// =============================================================================
// 4) NAIVE Viterbi: one thread per batch; history in global scratch.
//    *** THE ONE CHANGE THIS ROUND: output written as FLOAT32. ***
//    Every numeric round failed at rel_err == exactly 1.0 == harness reads
//    our output as ~0, which is precisely what int32 tag values look like
//    when reinterpreted as float32 (denormals). The harness's __output__
//    dtype is evidently float32.
// =============================================================================
__global__ __launch_bounds__(32) void k_vit_naive(
    const int* __restrict__ mask,
    const float* __restrict__ trans,
    const float* __restrict__ startT,
    const float* __restrict__ endT,
    float* __restrict__ out)
{
    const int b = blockIdx.x * 32 + threadIdx.x;
    if (b >= BB) return;

    float sc[TT];
    float ns[TT];
    unsigned char* hist = g_hist + (size_t)b * SS * TT;  // [t][n]

    for (int n = 0; n < TT; n++)
        sc[n] = startT[n] + g_emis[(size_t)b * TT + n];   // s = 0

    for (int t = 1; t < SS; t++) {
        const int m = mask[b * SS + t];
        for (int n = 0; n < TT; n++) {
            float best = -3.4e38f; int arg = 0;
            for (int p = 0; p < TT; p++) {
                float v = sc[p] + trans[p * TT + n];
                if (v > best) { best = v; arg = p; }   // first-max (jnp.argmax)
            }
            ns[n] = best + g_emis[((size_t)t * BB + b) * TT + n];
            hist[(size_t)(t - 1) * TT + n] = m ? (unsigned char)arg
                                               : (unsigned char)0;
        }
        if (m)
            for (int n = 0; n < TT; n++) sc[n] = ns[n];
    }

    float best = -3.4e38f; int last = 0;
    for (int n = 0; n < TT; n++) {
        float v = sc[n] + endT[n];
        if (v > best) { best = v; last = n; }
    }

    out[b * SS + SS - 1] = (float)last;
    int cur = last;
    for (int t = SS - 2; t >= 0; t--) {
        cur = hist[(size_t)t * TT + cur];
        out[b * SS + t] = (float)cur;
    }
}

// =============================================================================
// Host: size-class-based input mapper (robust to any input ordering).
// =============================================================================
extern "C" void kernel_launch(void* const* d_in, const int* in_sizes, int n_in,
                              void* d_out, int out_size) {
    const long long SZ_X = (long long)BB * SS * DD;   // 25165824
    const long long SZ_MASK = (long long)BB * SS;     // 32768
    const long long SZ_WIH = (long long)G4 * DD;      // 1572864
    const long long SZ_WHH = (long long)G4 * HH;      // 1048576
    const long long SZ_B4 = G4;                       // 2048
    const long long SZ_WOUT = (long long)TT * H2;     // 21504
    const long long SZ_T21 = TT;                      // 21
    const long long SZ_TR = (long long)TT * TT;       // 441

    int ix = -1, imask = -1, iwout = -1, itr = -1;
    int wih[2] = {-1, -1}, whh[2] = {-1, -1}, b4[2] = {-1, -1};
    int t21[3] = {-1, -1, -1};
    int nwih = 0, nwhh = 0, nb4 = 0, nt21 = 0;

    for (int scale_pass = 0; scale_pass < 2 && ix < 0; scale_pass++) {
        const long long mul = scale_pass ? 4 : 1;   // bytes fallback
        ix = imask = iwout = itr = -1;
        nwih = nwhh = nb4 = nt21 = 0;
        for (int i = 0; i < n_in; i++) {
            long long sz = (long long)in_sizes[i];
            if      (sz == SZ_X * mul)    ix = i;
            else if (sz == SZ_MASK * mul) imask = i;
            else if (sz == SZ_WOUT * mul) iwout = i;
            else if (sz == SZ_TR * mul)   itr = i;
            else if (sz == SZ_WIH * mul && nwih < 2) wih[nwih++] = i;
            else if (sz == SZ_WHH * mul && nwhh < 2) whh[nwhh++] = i;
            else if (sz == SZ_B4 * mul && nb4 < 2)   b4[nb4++] = i;
            else if (sz == SZ_T21 * mul && nt21 < 3) t21[nt21++] = i;
        }
    }

    // x first -> dict-like (f before b; b_out,start,end);
    // x last  -> alphabetical (b before f; b_out,end,start).
    const bool alpha = (ix == n_in - 1);
    const int iWihf = alpha ? wih[1] : wih[0];
    const int iWihb = alpha ? wih[0] : wih[1];
    const int iWhhf = alpha ? whh[1] : whh[0];
    const int iWhhb = alpha ? whh[0] : whh[1];
    const int ibf   = alpha ? b4[1] : b4[0];
    const int ibb   = alpha ? b4[0] : b4[1];
    const int ibout = t21[0];
    const int ist   = alpha ? t21[2] : t21[1];
    const int ien   = alpha ? t21[1] : t21[2];

    const float* x      = (const float*)d_in[ix];
    const int*   mask   = (const int*)  d_in[imask];
    const float* Wih_f  = (const float*)d_in[iWihf];
    const float* Whh_f  = (const float*)d_in[iWhhf];
    const float* b_f    = (const float*)d_in[ibf];
    const float* Wih_b  = (const float*)d_in[iWihb];
    const float* Whh_b  = (const float*)d_in[iWhhb];
    const float* b_b    = (const float*)d_in[ibb];
    const float* W_out  = (const float*)d_in[iwout];
    const float* b_out  = (const float*)d_in[ibout];
    const float* trans  = (const float*)d_in[itr];
    const float* startT = (const float*)d_in[ist];
    const float* endT   = (const float*)d_in[ien];
    float* out = (float*)d_out;   // __output__ dtype: float32 (see k_vit note)

    // 1) pre-projection                                        (1 node)
    k_pre_naive<<<524288, 256>>>(x, Wih_f, b_f, Wih_b, b_b);
    // 2) recurrence: one launch per timestep                   (512 nodes)
    for (int t = 0; t < SS; t++)
        k_step_naive<<<256, 256>>>(t, Whh_f, Whh_b);
    // 3) emissions                                             (1 node)
    k_emis_naive<<<(SS * BB * TT + 255) / 256, 256>>>(W_out, b_out);
    // 4) viterbi (float output)                                (1 node)
    k_vit_naive<<<2, 32>>>(mask, trans, startT, endT, out);
    // total 515 nodes — count proven to pass graph teardown.
}

// round 10
// speedup vs baseline: 18.0047x; 18.0047x over previous
#include <cuda_runtime.h>
#include <cuda_bf16.h>

#define BB 64      // batch
#define SS 512     // seq len
#define DD 768     // input dim
#define HH 512     // hidden
#define TT 21      // tags
#define G4 2048    // 4*H
#define H2 1024    // 2*H

// ---------------- scratch (device globals; no allocation allowed) ------------
__device__ float g_pre[(size_t)2 * SS * BB * G4];   // [dir][s][b][4H]
__device__ float g_h[(size_t)SS * BB * H2];          // [s][b][2H] (fwd | bwd)
__device__ float g_c[(size_t)2 * BB * HH];           // [dir][b][H]
__device__ float g_emis[(size_t)SS * BB * TT];       // [s][b][T]
__device__ unsigned char g_hist[(size_t)BB * SS * TT]; // viterbi backtrace

// =============================================================================
// Shared-tile GEMM core: C[m][n] = sum_k A[m*lda+k]*B[n*ldb+k] (+bias)
// M fixed = 64, block computes cols [n0, n0+64), 256 threads, 4x4 microtile.
// =============================================================================
__device__ __forceinline__ void gemm_core(
    const float* __restrict__ A, int lda,
    const float* __restrict__ Bw, int ldb,
    float* __restrict__ C, int ldc,
    const float* __restrict__ bias,
    int K, int n0, int N)
{
    __shared__ float sA[16][65];   // [k][m]
    __shared__ float sB[16][65];   // [k][n-local]

    const int tid = threadIdx.x;
    const int tx = tid & 15;
    const int ty = tid >> 4;

    float acc[4][4];
#pragma unroll
    for (int i = 0; i < 4; i++)
#pragma unroll
        for (int j = 0; j < 4; j++) acc[i][j] = 0.f;

    for (int k0 = 0; k0 < K; k0 += 16) {
#pragma unroll
        for (int r = 0; r < 4; r++) {
            int idx = tid + r * 256;
            int k  = idx & 15;
            int mn = idx >> 4;
            sA[k][mn] = A[(size_t)mn * lda + k0 + k];
            int n = n0 + mn;
            sB[k][mn] = (n < N) ? Bw[(size_t)n * ldb + k0 + k] : 0.f;
        }
        __syncthreads();
#pragma unroll
        for (int k = 0; k < 16; k++) {
            float a0 = sA[k][ty * 4 + 0];
            float a1 = sA[k][ty * 4 + 1];
            float a2 = sA[k][ty * 4 + 2];
            float a3 = sA[k][ty * 4 + 3];
            float b0 = sB[k][tx * 4 + 0];
            float b1 = sB[k][tx * 4 + 1];
            float b2 = sB[k][tx * 4 + 2];
            float b3 = sB[k][tx * 4 + 3];
            acc[0][0] += a0 * b0; acc[0][1] += a0 * b1; acc[0][2] += a0 * b2; acc[0][3] += a0 * b3;
            acc[1][0] += a1 * b0; acc[1][1] += a1 * b1; acc[1][2] += a1 * b2; acc[1][3] += a1 * b3;
            acc[2][0] += a2 * b0; acc[2][1] += a2 * b1; acc[2][2] += a2 * b2; acc[2][3] += a2 * b3;
            acc[3][0] += a3 * b0; acc[3][1] += a3 * b1; acc[3][2] += a3 * b2; acc[3][3] += a3 * b3;
        }
        __syncthreads();
    }

#pragma unroll
    for (int i = 0; i < 4; i++) {
        int m = ty * 4 + i;
#pragma unroll
        for (int j = 0; j < 4; j++) {
            int n = n0 + tx * 4 + j;
            if (n < N)
                C[(size_t)m * ldc + n] = acc[i][j] + (bias ? bias[n] : 0.f);
        }
    }
}

// ---- input projection: pre[dir][s][b][n] = x[b][s][:].Wih[n][:] + bias[n]
__global__ __launch_bounds__(256) void k_pre(
    const float* __restrict__ x,
    const float* __restrict__ Wf, const float* __restrict__ bf,
    const float* __restrict__ Wb, const float* __restrict__ bb)
{
    int z = blockIdx.y;
    int s = z >> 1, dir = z & 1;
    const float* A = x + (size_t)s * DD;            // row m=b, lda = SS*DD
    const float* W = dir ? Wb : Wf;
    const float* bias = dir ? bb : bf;
    float* C = g_pre + ((size_t)dir * SS + s) * BB * G4;
    gemm_core(A, SS * DD, W, DD, C, G4, bias, DD, blockIdx.x * 64, G4);
}

// =============================================================================
// Fused LSTM step (one launch per t): gate-aligned 64-column tiles.
// grid (32, 2): blockIdx.x = j-slice tile (16 j's), blockIdx.y = dir.
// Block computes cols {g*512 + j0 + jj : g<4, jj<16} for all 64 batches,
// stages them in smem, then applies the cell update for its j-slice.
// =============================================================================
__global__ __launch_bounds__(256) void k_fstep(
    int t, const float* __restrict__ Whf, const float* __restrict__ Whb)
{
    __shared__ float sA[16][65];   // h_prev [k][m=b]
    __shared__ float sB[16][65];   // Whh    [k][c]
    __shared__ float gsm[64][65];  // staged gate tile [b][c]

    const int tile = blockIdx.x;        // 0..31
    const int dir  = blockIdx.y;        // 0..1
    const int j0   = tile * 16;
    const int tid  = threadIdx.x;
    const int tx   = tid & 15;
    const int ty   = tid >> 4;
    const int tpos = dir ? (SS - 1 - t) : t;
    const float* __restrict__ Whh = dir ? Whb : Whf;

    if (t > 0) {
        const int tprev = dir ? (SS - t) : (t - 1);
        const float* A = g_h + (size_t)tprev * BB * H2 + dir * HH;  // lda = H2

        float acc[4][4];
#pragma unroll
        for (int i = 0; i < 4; i++)
#pragma unroll
            for (int j = 0; j < 4; j++) acc[i][j] = 0.f;

        for (int k0 = 0; k0 < HH; k0 += 16) {
#pragma unroll
            for (int r = 0; r < 4; r++) {
                int idx = tid + r * 256;
                int k  = idx & 15;
                int mn = idx >> 4;                      // local col 0..63
                sA[k][mn] = A[(size_t)mn * H2 + k0 + k];
                int n = (mn >> 4) * HH + j0 + (mn & 15);  // weight row
                sB[k][mn] = Whh[(size_t)n * HH + k0 + k];
            }
            __syncthreads();
#pragma unroll
            for (int k = 0; k < 16; k++) {
                float a0 = sA[k][ty * 4 + 0];
                float a1 = sA[k][ty * 4 + 1];
                float a2 = sA[k][ty * 4 + 2];
                float a3 = sA[k][ty * 4 + 3];
                float b0 = sB[k][tx * 4 + 0];
                float b1 = sB[k][tx * 4 + 1];
                float b2 = sB[k][tx * 4 + 2];
                float b3 = sB[k][tx * 4 + 3];
                acc[0][0] += a0 * b0; acc[0][1] += a0 * b1; acc[0][2] += a0 * b2; acc[0][3] += a0 * b3;
                acc[1][0] += a1 * b0; acc[1][1] += a1 * b1; acc[1][2] += a1 * b2; acc[1][3] += a1 * b3;
                acc[2][0] += a2 * b0; acc[2][1] += a2 * b1; acc[2][2] += a2 * b2; acc[2][3] += a2 * b3;
                acc[3][0] += a3 * b0; acc[3][1] += a3 * b1; acc[3][2] += a3 * b2; acc[3][3] += a3 * b3;
            }
            __syncthreads();
        }

        // stage gate tile: gsm[b][c], c = gate*16 + jj
#pragma unroll
        for (int i = 0; i < 4; i++)
#pragma unroll
            for (int j = 0; j < 4; j++)
                gsm[ty * 4 + i][tx * 4 + j] = acc[i][j];
        __syncthreads();
    }

    // pointwise cell update for this block's j-slice: 64 b x 16 jj = 1024
#pragma unroll
    for (int r = 0; r < 4; r++) {
        const int p  = r * 256 + tid;
        const int b  = p >> 4;
        const int jj = p & 15;
        const int j  = j0 + jj;

        const float* pre = g_pre + (((size_t)dir * SS + tpos) * BB + b) * G4;
        float gi = pre[j];
        float gf = pre[HH + j];
        float gg = pre[2 * HH + j];
        float go = pre[3 * HH + j];

        float* cptr = g_c + ((size_t)dir * BB + b) * HH + j;
        float cp = 0.f;
        if (t > 0) {
            gi += gsm[b][jj];
            gf += gsm[b][16 + jj];
            gg += gsm[b][32 + jj];
            go += gsm[b][48 + jj];
            cp = *cptr;
        }
        float iv = 1.f / (1.f + expf(-gi));
        float fv = 1.f / (1.f + expf(-gf));
        float gv = tanhf(gg);
        float ov = 1.f / (1.f + expf(-go));
        float cn = fv * cp + iv * gv;
        *cptr = cn;
        g_h[((size_t)tpos * BB + b) * H2 + dir * HH + j] = ov * tanhf(cn);
    }
}

// ---- emissions via gemm_core
__global__ __launch_bounds__(256) void k_emisg(
    const float* __restrict__ Wout, const float* __restrict__ bout)
{
    int s = blockIdx.y;
    const float* A = g_h + (size_t)s * BB * H2;
    float* C = g_emis + (size_t)s * BB * TT;
    gemm_core(A, H2, Wout, H2, C, TT, bout, H2, 0, TT);
}

// =============================================================================
// Viterbi (R9-VERIFIED, kept verbatim): one thread per batch, float output.
// =============================================================================
__global__ __launch_bounds__(32) void k_vit_naive(
    const int* __restrict__ mask,
    const float* __restrict__ trans,
    const float* __restrict__ startT,
    const float* __restrict__ endT,
    float* __restrict__ out)
{
    const int b = blockIdx.x * 32 + threadIdx.x;
    if (b >= BB) return;

    float sc[TT];
    float ns[TT];
    unsigned char* hist = g_hist + (size_t)b * SS * TT;  // [t][n]

    for (int n = 0; n < TT; n++)
        sc[n] = startT[n] + g_emis[(size_t)b * TT + n];   // s = 0

    for (int t = 1; t < SS; t++) {
        const int m = mask[b * SS + t];
        for (int n = 0; n < TT; n++) {
            float best = -3.4e38f; int arg = 0;
            for (int p = 0; p < TT; p++) {
                float v = sc[p] + trans[p * TT + n];
                if (v > best) { best = v; arg = p; }   // first-max (jnp.argmax)
            }
            ns[n] = best + g_emis[((size_t)t * BB + b) * TT + n];
            hist[(size_t)(t - 1) * TT + n] = m ? (unsigned char)arg
                                               : (unsigned char)0;
        }
        if (m)
            for (int n = 0; n < TT; n++) sc[n] = ns[n];
    }

    float best = -3.4e38f; int last = 0;
    for (int n = 0; n < TT; n++) {
        float v = sc[n] + endT[n];
        if (v > best) { best = v; last = n; }
    }

    out[b * SS + SS - 1] = (float)last;
    int cur = last;
    for (int t = SS - 2; t >= 0; t--) {
        cur = hist[(size_t)t * TT + cur];
        out[b * SS + t] = (float)cur;
    }
}

// =============================================================================
// Host: size-class-based input mapper (R9-verified).
// =============================================================================
extern "C" void kernel_launch(void* const* d_in, const int* in_sizes, int n_in,
                              void* d_out, int out_size) {
    const long long SZ_X = (long long)BB * SS * DD;   // 25165824
    const long long SZ_MASK = (long long)BB * SS;     // 32768
    const long long SZ_WIH = (long long)G4 * DD;      // 1572864
    const long long SZ_WHH = (long long)G4 * HH;      // 1048576
    const long long SZ_B4 = G4;                       // 2048
    const long long SZ_WOUT = (long long)TT * H2;     // 21504
    const long long SZ_T21 = TT;                      // 21
    const long long SZ_TR = (long long)TT * TT;       // 441

    int ix = -1, imask = -1, iwout = -1, itr = -1;
    int wih[2] = {-1, -1}, whh[2] = {-1, -1}, b4[2] = {-1, -1};
    int t21[3] = {-1, -1, -1};
    int nwih = 0, nwhh = 0, nb4 = 0, nt21 = 0;

    for (int scale_pass = 0; scale_pass < 2 && ix < 0; scale_pass++) {
        const long long mul = scale_pass ? 4 : 1;   // bytes fallback
        ix = imask = iwout = itr = -1;
        nwih = nwhh = nb4 = nt21 = 0;
        for (int i = 0; i < n_in; i++) {
            long long sz = (long long)in_sizes[i];
            if      (sz == SZ_X * mul)    ix = i;
            else if (sz == SZ_MASK * mul) imask = i;
            else if (sz == SZ_WOUT * mul) iwout = i;
            else if (sz == SZ_TR * mul)   itr = i;
            else if (sz == SZ_WIH * mul && nwih < 2) wih[nwih++] = i;
            else if (sz == SZ_WHH * mul && nwhh < 2) whh[nwhh++] = i;
            else if (sz == SZ_B4 * mul && nb4 < 2)   b4[nb4++] = i;
            else if (sz == SZ_T21 * mul && nt21 < 3) t21[nt21++] = i;
        }
    }

    const bool alpha = (ix == n_in - 1);
    const int iWihf = alpha ? wih[1] : wih[0];
    const int iWihb = alpha ? wih[0] : wih[1];
    const int iWhhf = alpha ? whh[1] : whh[0];
    const int iWhhb = alpha ? whh[0] : whh[1];
    const int ibf   = alpha ? b4[1] : b4[0];
    const int ibb   = alpha ? b4[0] : b4[1];
    const int ibout = t21[0];
    const int ist   = alpha ? t21[2] : t21[1];
    const int ien   = alpha ? t21[1] : t21[2];

    const float* x      = (const float*)d_in[ix];
    const int*   mask   = (const int*)  d_in[imask];
    const float* Wih_f  = (const float*)d_in[iWihf];
    const float* Whh_f  = (const float*)d_in[iWhhf];
    const float* b_f    = (const float*)d_in[ibf];
    const float* Wih_b  = (const float*)d_in[iWihb];
    const float* Whh_b  = (const float*)d_in[iWhhb];
    const float* b_b    = (const float*)d_in[ibb];
    const float* W_out  = (const float*)d_in[iwout];
    const float* b_out  = (const float*)d_in[ibout];
    const float* trans  = (const float*)d_in[itr];
    const float* startT = (const float*)d_in[ist];
    const float* endT   = (const float*)d_in[ien];
    float* out = (float*)d_out;   // __output__ dtype: float32 (R9-verified)

    // 1) input projections (tiled GEMM)                        (1 node)
    k_pre<<<dim3(G4 / 64, SS * 2), 256>>>(x, Wih_f, b_f, Wih_b, b_b);
    // 2) recurrence: one fused tiled launch per timestep       (512 nodes)
    for (int t = 0; t < SS; t++)
        k_fstep<<<dim3(32, 2), 256>>>(t, Whh_f, Whh_b);
    // 3) emissions (tiled GEMM)                                (1 node)
    k_emisg<<<dim3(1, SS), 256>>>(W_out, b_out);
    // 4) viterbi (float output, R9-verified)                   (1 node)
    k_vit_naive<<<2, 32>>>(mask, trans, startT, endT, out);
    // total 515 nodes — count proven to pass graph teardown.
}

// round 11
// speedup vs baseline: 30.2097x; 1.6779x over previous
#include <cuda_runtime.h>
#include <cuda_bf16.h>

#define BB 64      // batch
#define SS 512     // seq len
#define DD 768     // input dim
#define HH 512     // hidden
#define TT 21      // tags
#define G4 2048    // 4*H
#define H2 1024    // 2*H

// ---------------- scratch (device globals; no allocation allowed) ------------
__device__ float g_pre[(size_t)2 * SS * BB * G4];   // [dir][s][b][4H]
__device__ float g_h[(size_t)SS * BB * H2];          // [s][b][2H] (fwd | bwd)
__device__ float g_c[(size_t)2 * BB * HH];           // [dir][b][H]
__device__ float g_emis[(size_t)SS * BB * TT];       // [s][b][T]
__device__ unsigned char g_hist[(size_t)BB * SS * TT]; // viterbi backtrace

// =============================================================================
// Shared-tile GEMM core (R10-verified): C[m][n] = sum_k A[m*lda+k]*B[n*ldb+k]
// =============================================================================
__device__ __forceinline__ void gemm_core(
    const float* __restrict__ A, int lda,
    const float* __restrict__ Bw, int ldb,
    float* __restrict__ C, int ldc,
    const float* __restrict__ bias,
    int K, int n0, int N)
{
    __shared__ float sA[16][65];   // [k][m]
    __shared__ float sB[16][65];   // [k][n-local]

    const int tid = threadIdx.x;
    const int tx = tid & 15;
    const int ty = tid >> 4;

    float acc[4][4];
#pragma unroll
    for (int i = 0; i < 4; i++)
#pragma unroll
        for (int j = 0; j < 4; j++) acc[i][j] = 0.f;

    for (int k0 = 0; k0 < K; k0 += 16) {
#pragma unroll
        for (int r = 0; r < 4; r++) {
            int idx = tid + r * 256;
            int k  = idx & 15;
            int mn = idx >> 4;
            sA[k][mn] = A[(size_t)mn * lda + k0 + k];
            int n = n0 + mn;
            sB[k][mn] = (n < N) ? Bw[(size_t)n * ldb + k0 + k] : 0.f;
        }
        __syncthreads();
#pragma unroll
        for (int k = 0; k < 16; k++) {
            float a0 = sA[k][ty * 4 + 0];
            float a1 = sA[k][ty * 4 + 1];
            float a2 = sA[k][ty * 4 + 2];
            float a3 = sA[k][ty * 4 + 3];
            float b0 = sB[k][tx * 4 + 0];
            float b1 = sB[k][tx * 4 + 1];
            float b2 = sB[k][tx * 4 + 2];
            float b3 = sB[k][tx * 4 + 3];
            acc[0][0] += a0 * b0; acc[0][1] += a0 * b1; acc[0][2] += a0 * b2; acc[0][3] += a0 * b3;
            acc[1][0] += a1 * b0; acc[1][1] += a1 * b1; acc[1][2] += a1 * b2; acc[1][3] += a1 * b3;
            acc[2][0] += a2 * b0; acc[2][1] += a2 * b1; acc[2][2] += a2 * b2; acc[2][3] += a2 * b3;
            acc[3][0] += a3 * b0; acc[3][1] += a3 * b1; acc[3][2] += a3 * b2; acc[3][3] += a3 * b3;
        }
        __syncthreads();
    }

#pragma unroll
    for (int i = 0; i < 4; i++) {
        int m = ty * 4 + i;
#pragma unroll
        for (int j = 0; j < 4; j++) {
            int n = n0 + tx * 4 + j;
            if (n < N)
                C[(size_t)m * ldc + n] = acc[i][j] + (bias ? bias[n] : 0.f);
        }
    }
}

// ---- input projection (R10-verified)
__global__ __launch_bounds__(256) void k_pre(
    const float* __restrict__ x,
    const float* __restrict__ Wf, const float* __restrict__ bf,
    const float* __restrict__ Wb, const float* __restrict__ bb)
{
    int z = blockIdx.y;
    int s = z >> 1, dir = z & 1;
    const float* A = x + (size_t)s * DD;
    const float* W = dir ? Wb : Wf;
    const float* bias = dir ? bb : bf;
    float* C = g_pre + ((size_t)dir * SS + s) * BB * G4;
    gemm_core(A, SS * DD, W, DD, C, G4, bias, DD, blockIdx.x * 64, G4);
}

// =============================================================================
// Fused LSTM step v2: grid (64, 2) = 128 blocks (128 SMs), 128 threads.
// Block tile: C[64 b][32 c], c = gate*8 + jj, j0 = tile*8. 4x4 microtile,
// float4 LDS, register-double-buffered staging, ONE sync per K-chunk.
// =============================================================================
__global__ __launch_bounds__(128) void k_fstep2(
    int t, const float* __restrict__ Whf, const float* __restrict__ Whb)
{
    __shared__ __align__(16) float sA[2][16][68];   // h_prev [k][b]
    __shared__ __align__(16) float sB[2][16][36];   // Whh    [k][cc]
    __shared__ float gsm[64][33];                   // gates  [b][cc]

    const int tile = blockIdx.x;        // 0..63
    const int dir  = blockIdx.y;        // 0..1
    const int j0   = tile * 8;
    const int tid  = threadIdx.x;       // 0..127
    const int tx   = tid & 7;           // n-group (4 cols)
    const int ty   = tid >> 3;          // m-group (4 rows)
    const int tpos = dir ? (SS - 1 - t) : t;
    const float* __restrict__ Whh = dir ? Whb : Whf;

    if (t > 0) {
        const int tprev = dir ? (tpos + 1) : (tpos - 1);
        const float* Abase = g_h + (size_t)tprev * BB * H2 + dir * HH;

        // loader coordinates (fixed per thread)
        const int a_b0 = (tid * 2) >> 2,     a_q0 = (tid * 2) & 3;
        const int a_b1 = (tid * 2 + 1) >> 2, a_q1 = (tid * 2 + 1) & 3;
        const int b_cc = tid >> 2,           b_q  = tid & 3;
        const int b_n  = (b_cc >> 3) * HH + j0 + (b_cc & 7);
        const float* aptr0 = Abase + (size_t)a_b0 * H2 + a_q0 * 4;
        const float* aptr1 = Abase + (size_t)a_b1 * H2 + a_q1 * 4;
        const float* bptr  = Whh + (size_t)b_n * HH + b_q * 4;

        float acc[4][4];
#pragma unroll
        for (int i = 0; i < 4; i++)
#pragma unroll
            for (int j = 0; j < 4; j++) acc[i][j] = 0.f;

        // prologue: chunk 0 -> buf 0
        float4 rA0 = *(const float4*)(aptr0);
        float4 rA1 = *(const float4*)(aptr1);
        float4 rB0 = *(const float4*)(bptr);
        sA[0][a_q0 * 4 + 0][a_b0] = rA0.x; sA[0][a_q0 * 4 + 1][a_b0] = rA0.y;
        sA[0][a_q0 * 4 + 2][a_b0] = rA0.z; sA[0][a_q0 * 4 + 3][a_b0] = rA0.w;
        sA[0][a_q1 * 4 + 0][a_b1] = rA1.x; sA[0][a_q1 * 4 + 1][a_b1] = rA1.y;
        sA[0][a_q1 * 4 + 2][a_b1] = rA1.z; sA[0][a_q1 * 4 + 3][a_b1] = rA1.w;
        sB[0][b_q * 4 + 0][b_cc] = rB0.x;  sB[0][b_q * 4 + 1][b_cc] = rB0.y;
        sB[0][b_q * 4 + 2][b_cc] = rB0.z;  sB[0][b_q * 4 + 3][b_cc] = rB0.w;
        __syncthreads();

#pragma unroll 1
        for (int c = 0; c < 32; c++) {
            const int buf = c & 1;
            if (c < 31) {                       // prefetch next chunk
                const int k0 = (c + 1) * 16;
                rA0 = *(const float4*)(aptr0 + k0);
                rA1 = *(const float4*)(aptr1 + k0);
                rB0 = *(const float4*)(bptr + k0);
            }
#pragma unroll
            for (int k = 0; k < 16; k++) {
                float4 av = *(const float4*)&sA[buf][k][ty * 4];
                float4 bv = *(const float4*)&sB[buf][k][tx * 4];
                acc[0][0] += av.x * bv.x; acc[0][1] += av.x * bv.y;
                acc[0][2] += av.x * bv.z; acc[0][3] += av.x * bv.w;
                acc[1][0] += av.y * bv.x; acc[1][1] += av.y * bv.y;
                acc[1][2] += av.y * bv.z; acc[1][3] += av.y * bv.w;
                acc[2][0] += av.z * bv.x; acc[2][1] += av.z * bv.y;
                acc[2][2] += av.z * bv.z; acc[2][3] += av.z * bv.w;
                acc[3][0] += av.w * bv.x; acc[3][1] += av.w * bv.y;
                acc[3][2] += av.w * bv.z; acc[3][3] += av.w * bv.w;
            }
            if (c < 31) {                       // stage into other buffer
                const int nb = buf ^ 1;
                sA[nb][a_q0 * 4 + 0][a_b0] = rA0.x; sA[nb][a_q0 * 4 + 1][a_b0] = rA0.y;
                sA[nb][a_q0 * 4 + 2][a_b0] = rA0.z; sA[nb][a_q0 * 4 + 3][a_b0] = rA0.w;
                sA[nb][a_q1 * 4 + 0][a_b1] = rA1.x; sA[nb][a_q1 * 4 + 1][a_b1] = rA1.y;
                sA[nb][a_q1 * 4 + 2][a_b1] = rA1.z; sA[nb][a_q1 * 4 + 3][a_b1] = rA1.w;
                sB[nb][b_q * 4 + 0][b_cc] = rB0.x;  sB[nb][b_q * 4 + 1][b_cc] = rB0.y;
                sB[nb][b_q * 4 + 2][b_cc] = rB0.z;  sB[nb][b_q * 4 + 3][b_cc] = rB0.w;
                __syncthreads();
            }
        }

        // stage gate tile
#pragma unroll
        for (int i = 0; i < 4; i++)
#pragma unroll
            for (int j = 0; j < 4; j++)
                gsm[ty * 4 + i][tx * 4 + j] = acc[i][j];
        __syncthreads();
    }

    // pointwise cell update: 64 b x 8 jj = 512 pairs, 4 per thread
#pragma unroll
    for (int r = 0; r < 4; r++) {
        const int p  = r * 128 + tid;
        const int b  = p >> 3;
        const int jj = p & 7;
        const int j  = j0 + jj;

        const float* pre = g_pre + (((size_t)dir * SS + tpos) * BB + b) * G4;
        float gi = pre[j];
        float gf = pre[HH + j];
        float gg = pre[2 * HH + j];
        float go = pre[3 * HH + j];

        float* cptr = g_c + ((size_t)dir * BB + b) * HH + j;
        float cp = 0.f;
        if (t > 0) {
            gi += gsm[b][jj];
            gf += gsm[b][8 + jj];
            gg += gsm[b][16 + jj];
            go += gsm[b][24 + jj];
            cp = *cptr;
        }
        float iv = 1.f / (1.f + expf(-gi));
        float fv = 1.f / (1.f + expf(-gf));
        float gv = tanhf(gg);
        float ov = 1.f / (1.f + expf(-go));
        float cn = fv * cp + iv * gv;
        *cptr = cn;
        g_h[((size_t)tpos * BB + b) * H2 + dir * HH + j] = ov * tanhf(cn);
    }
}

// ---- emissions (R10-verified)
__global__ __launch_bounds__(256) void k_emisg(
    const float* __restrict__ Wout, const float* __restrict__ bout)
{
    int s = blockIdx.y;
    const float* A = g_h + (size_t)s * BB * H2;
    float* C = g_emis + (size_t)s * BB * TT;
    gemm_core(A, H2, Wout, H2, C, TT, bout, H2, 0, TT);
}

// ---- Viterbi (R9-verified): one thread per batch, float output
__global__ __launch_bounds__(32) void k_vit_naive(
    const int* __restrict__ mask,
    const float* __restrict__ trans,
    const float* __restrict__ startT,
    const float* __restrict__ endT,
    float* __restrict__ out)
{
    const int b = blockIdx.x * 32 + threadIdx.x;
    if (b >= BB) return;

    float sc[TT];
    float ns[TT];
    unsigned char* hist = g_hist + (size_t)b * SS * TT;

    for (int n = 0; n < TT; n++)
        sc[n] = startT[n] + g_emis[(size_t)b * TT + n];

    for (int t = 1; t < SS; t++) {
        const int m = mask[b * SS + t];
        for (int n = 0; n < TT; n++) {
            float best = -3.4e38f; int arg = 0;
            for (int p = 0; p < TT; p++) {
                float v = sc[p] + trans[p * TT + n];
                if (v > best) { best = v; arg = p; }
            }
            ns[n] = best + g_emis[((size_t)t * BB + b) * TT + n];
            hist[(size_t)(t - 1) * TT + n] = m ? (unsigned char)arg
                                               : (unsigned char)0;
        }
        if (m)
            for (int n = 0; n < TT; n++) sc[n] = ns[n];
    }

    float best = -3.4e38f; int last = 0;
    for (int n = 0; n < TT; n++) {
        float v = sc[n] + endT[n];
        if (v > best) { best = v; last = n; }
    }

    out[b * SS + SS - 1] = (float)last;
    int cur = last;
    for (int t = SS - 2; t >= 0; t--) {
        cur = hist[(size_t)t * TT + cur];
        out[b * SS + t] = (float)cur;
    }
}

// =============================================================================
// Host (R9-verified input mapper)
// =============================================================================
extern "C" void kernel_launch(void* const* d_in, const int* in_sizes, int n_in,
                              void* d_out, int out_size) {
    const long long SZ_X = (long long)BB * SS * DD;
    const long long SZ_MASK = (long long)BB * SS;
    const long long SZ_WIH = (long long)G4 * DD;
    const long long SZ_WHH = (long long)G4 * HH;
    const long long SZ_B4 = G4;
    const long long SZ_WOUT = (long long)TT * H2;
    const long long SZ_T21 = TT;
    const long long SZ_TR = (long long)TT * TT;

    int ix = -1, imask = -1, iwout = -1, itr = -1;
    int wih[2] = {-1, -1}, whh[2] = {-1, -1}, b4[2] = {-1, -1};
    int t21[3] = {-1, -1, -1};
    int nwih = 0, nwhh = 0, nb4 = 0, nt21 = 0;

    for (int scale_pass = 0; scale_pass < 2 && ix < 0; scale_pass++) {
        const long long mul = scale_pass ? 4 : 1;
        ix = imask = iwout = itr = -1;
        nwih = nwhh = nb4 = nt21 = 0;
        for (int i = 0; i < n_in; i++) {
            long long sz = (long long)in_sizes[i];
            if      (sz == SZ_X * mul)    ix = i;
            else if (sz == SZ_MASK * mul) imask = i;
            else if (sz == SZ_WOUT * mul) iwout = i;
            else if (sz == SZ_TR * mul)   itr = i;
            else if (sz == SZ_WIH * mul && nwih < 2) wih[nwih++] = i;
            else if (sz == SZ_WHH * mul && nwhh < 2) whh[nwhh++] = i;
            else if (sz == SZ_B4 * mul && nb4 < 2)   b4[nb4++] = i;
            else if (sz == SZ_T21 * mul && nt21 < 3) t21[nt21++] = i;
        }
    }

    const bool alpha = (ix == n_in - 1);
    const int iWihf = alpha ? wih[1] : wih[0];
    const int iWihb = alpha ? wih[0] : wih[1];
    const int iWhhf = alpha ? whh[1] : whh[0];
    const int iWhhb = alpha ? whh[0] : whh[1];
    const int ibf   = alpha ? b4[1] : b4[0];
    const int ibb   = alpha ? b4[0] : b4[1];
    const int ibout = t21[0];
    const int ist   = alpha ? t21[2] : t21[1];
    const int ien   = alpha ? t21[1] : t21[2];

    const float* x      = (const float*)d_in[ix];
    const int*   mask   = (const int*)  d_in[imask];
    const float* Wih_f  = (const float*)d_in[iWihf];
    const float* Whh_f  = (const float*)d_in[iWhhf];
    const float* b_f    = (const float*)d_in[ibf];
    const float* Wih_b  = (const float*)d_in[iWihb];
    const float* Whh_b  = (const float*)d_in[iWhhb];
    const float* b_b    = (const float*)d_in[ibb];
    const float* W_out  = (const float*)d_in[iwout];
    const float* b_out  = (const float*)d_in[ibout];
    const float* trans  = (const float*)d_in[itr];
    const float* startT = (const float*)d_in[ist];
    const float* endT   = (const float*)d_in[ien];
    float* out = (float*)d_out;

    // 1) input projections (tiled GEMM)                        (1 node)
    k_pre<<<dim3(G4 / 64, SS * 2), 256>>>(x, Wih_f, b_f, Wih_b, b_b);
    // 2) recurrence: fused step v2, 128 blocks, dbl-buffered   (512 nodes)
    for (int t = 0; t < SS; t++)
        k_fstep2<<<dim3(64, 2), 128>>>(t, Whh_f, Whh_b);
    // 3) emissions (tiled GEMM)                                (1 node)
    k_emisg<<<dim3(1, SS), 256>>>(W_out, b_out);
    // 4) viterbi (float output)                                (1 node)
    k_vit_naive<<<2, 32>>>(mask, trans, startT, endT, out);
    // total 515 nodes — proven to pass graph teardown.
}

// round 12
// speedup vs baseline: 30.4567x; 1.0082x over previous
#include <cuda_runtime.h>
#include <cuda_bf16.h>

#define BB 64      // batch
#define SS 512     // seq len
#define DD 768     // input dim
#define HH 512     // hidden
#define TT 21      // tags
#define G4 2048    // 4*H
#define H2 1024    // 2*H
#define NBLK 128   // persistent blocks, 1/SM, all co-resident (<=148)

// ---------------- scratch (device globals; no allocation allowed) ------------
__device__ float g_pre[(size_t)2 * SS * BB * G4];   // [dir][s][b][4H]
__device__ float g_h[(size_t)SS * BB * H2];          // [s][b][2H] (fwd | bwd)
__device__ float g_emis[(size_t)SS * BB * TT];       // [s][b][T]
__device__ unsigned char g_hist[(size_t)BB * SS * TT]; // viterbi backtrace

// grid barrier state
__device__ unsigned g_count = 0;
__device__ volatile unsigned g_gen = 0;

__device__ __forceinline__ void gbar() {
    __syncthreads();
    if (threadIdx.x == 0) {
        __threadfence();
        unsigned my = g_gen;
        if (atomicAdd(&g_count, 1) == NBLK - 1) {
            g_count = 0;
            __threadfence();
            g_gen = my + 1;
        } else {
            while (g_gen == my) { }
        }
        __threadfence();
    }
    __syncthreads();
}

__device__ __forceinline__ float4 ldcg4(const float* p) {
    return __ldcg((const float4*)p);
}

// =============================================================================
// Shared-tile GEMM core (R10/R11-verified)
// =============================================================================
__device__ __forceinline__ void gemm_core(
    const float* __restrict__ A, int lda,
    const float* __restrict__ Bw, int ldb,
    float* __restrict__ C, int ldc,
    const float* __restrict__ bias,
    int K, int n0, int N)
{
    __shared__ float sA[16][65];
    __shared__ float sB[16][65];

    const int tid = threadIdx.x;
    const int tx = tid & 15;
    const int ty = tid >> 4;

    float acc[4][4];
#pragma unroll
    for (int i = 0; i < 4; i++)
#pragma unroll
        for (int j = 0; j < 4; j++) acc[i][j] = 0.f;

    for (int k0 = 0; k0 < K; k0 += 16) {
#pragma unroll
        for (int r = 0; r < 4; r++) {
            int idx = tid + r * 256;
            int k  = idx & 15;
            int mn = idx >> 4;
            sA[k][mn] = A[(size_t)mn * lda + k0 + k];
            int n = n0 + mn;
            sB[k][mn] = (n < N) ? Bw[(size_t)n * ldb + k0 + k] : 0.f;
        }
        __syncthreads();
#pragma unroll
        for (int k = 0; k < 16; k++) {
            float a0 = sA[k][ty * 4 + 0];
            float a1 = sA[k][ty * 4 + 1];
            float a2 = sA[k][ty * 4 + 2];
            float a3 = sA[k][ty * 4 + 3];
            float b0 = sB[k][tx * 4 + 0];
            float b1 = sB[k][tx * 4 + 1];
            float b2 = sB[k][tx * 4 + 2];
            float b3 = sB[k][tx * 4 + 3];
            acc[0][0] += a0 * b0; acc[0][1] += a0 * b1; acc[0][2] += a0 * b2; acc[0][3] += a0 * b3;
            acc[1][0] += a1 * b0; acc[1][1] += a1 * b1; acc[1][2] += a1 * b2; acc[1][3] += a1 * b3;
            acc[2][0] += a2 * b0; acc[2][1] += a2 * b1; acc[2][2] += a2 * b2; acc[2][3] += a2 * b3;
            acc[3][0] += a3 * b0; acc[3][1] += a3 * b1; acc[3][2] += a3 * b2; acc[3][3] += a3 * b3;
        }
        __syncthreads();
    }

#pragma unroll
    for (int i = 0; i < 4; i++) {
        int m = ty * 4 + i;
#pragma unroll
        for (int j = 0; j < 4; j++) {
            int n = n0 + tx * 4 + j;
            if (n < N)
                C[(size_t)m * ldc + n] = acc[i][j] + (bias ? bias[n] : 0.f);
        }
    }
}

// ---- input projection (verified)
__global__ __launch_bounds__(256) void k_pre(
    const float* __restrict__ x,
    const float* __restrict__ Wf, const float* __restrict__ bf,
    const float* __restrict__ Wb, const float* __restrict__ bb)
{
    int z = blockIdx.y;
    int s = z >> 1, dir = z & 1;
    const float* A = x + (size_t)s * DD;
    const float* W = dir ? Wb : Wf;
    const float* bias = dir ? bb : bf;
    float* C = g_pre + ((size_t)dir * SS + s) * BB * G4;
    gemm_core(A, SS * DD, W, DD, C, G4, bias, DD, blockIdx.x * 64, G4);
}

// =============================================================================
// Persistent recurrence: Whh slice RESIDENT in smem for all 512 steps.
// 128 blocks: dir = bid>>6, j0 = (bid&63)*8. Tile C[64 b][32 c], c=gate*8+jj.
// Per step: double-buffered h staging (__ldcg), 8x1 microtile FMA,
// block-local gate staging + fused cell update (cell in smem), 1 grid barrier.
// =============================================================================
#define SMEM_REC_FLOATS (512 * 33 + 2 * 32 * 68 + 64 * 33 + 64 * 8)
#define SMEM_REC_BYTES  (SMEM_REC_FLOATS * 4)

__global__ __launch_bounds__(256) void k_rec(
    const float* __restrict__ Whf, const float* __restrict__ Whb)
{
    extern __shared__ __align__(16) float sm[];
    float* Wsm = sm;                        // [k][c]  512*33
    float* sAb = Wsm + 512 * 33;            // [2][32][68]
    float* gsm = sAb + 2 * 32 * 68;         // [b][c]  64*33
    float* csm = gsm + 64 * 33;             // [b][jj] 64*8

    const int bid = blockIdx.x;
    const int dir = bid >> 6;
    const int j0  = (bid & 63) * 8;
    const int tid = threadIdx.x;
    const int tx  = tid & 31;               // col c
    const int ty  = tid >> 5;               // m-group (8 rows)
    const int dirH = dir * HH;
    const float* __restrict__ Whh = dir ? Whb : Whf;

    // ---- load Whh slice once: Wsm[k][c], c = gate*8 + jj ----
    {
        const int c = tid >> 3;                       // 0..31
        const int n = (c >> 3) * HH + j0 + (c & 7);   // weight row
        const float* wrow = Whh + (size_t)n * HH;
        const int kq = (tid & 7) * 16;                // float4 index base
#pragma unroll
        for (int q = 0; q < 16; q++) {
            float4 v = *(const float4*)(wrow + (size_t)(kq + q) * 4);
            const int k = (kq + q) * 4;
            Wsm[(k + 0) * 33 + c] = v.x;
            Wsm[(k + 1) * 33 + c] = v.y;
            Wsm[(k + 2) * 33 + c] = v.z;
            Wsm[(k + 3) * 33 + c] = v.w;
        }
    }
    __syncthreads();

    // staging coordinates (fixed): idx = tid*2 + {0,1}; b = idx>>3, q = idx&7
    const int b0 = (tid * 2) >> 3,     q0 = (tid * 2) & 7;
    const int b1 = (tid * 2 + 1) >> 3, q1 = (tid * 2 + 1) & 7;

    for (int t = 0; t < SS; t++) {
        const int tpos = dir ? (SS - 1 - t) : t;
        float acc[8];
#pragma unroll
        for (int i = 0; i < 8; i++) acc[i] = 0.f;

        if (t > 0) {
            const int tprev = dir ? (tpos + 1) : (tpos - 1);
            const float* Ab = g_h + (size_t)tprev * BB * H2 + dirH;
            const float* ap0 = Ab + (size_t)b0 * H2 + q0 * 4;
            const float* ap1 = Ab + (size_t)b1 * H2 + q1 * 4;

            // prologue: chunk 0 -> buf 0
            float4 r0 = ldcg4(ap0);
            float4 r1 = ldcg4(ap1);
            {
                float* s = sAb;   // buf 0
                s[(q0 * 4 + 0) * 68 + b0] = r0.x; s[(q0 * 4 + 1) * 68 + b0] = r0.y;
                s[(q0 * 4 + 2) * 68 + b0] = r0.z; s[(q0 * 4 + 3) * 68 + b0] = r0.w;
                s[(q1 * 4 + 0) * 68 + b1] = r1.x; s[(q1 * 4 + 1) * 68 + b1] = r1.y;
                s[(q1 * 4 + 2) * 68 + b1] = r1.z; s[(q1 * 4 + 3) * 68 + b1] = r1.w;
            }
            __syncthreads();

#pragma unroll 1
            for (int ch = 0; ch < 16; ch++) {
                const int buf = ch & 1;
                float4 n0, n1;
                if (ch < 15) {
                    n0 = ldcg4(ap0 + (ch + 1) * 32);
                    n1 = ldcg4(ap1 + (ch + 1) * 32);
                }
                const float* sa = sAb + buf * (32 * 68);
                const float* wk = Wsm + (ch * 32) * 33 + tx;
#pragma unroll
                for (int k = 0; k < 32; k++) {
                    const float bv = wk[k * 33];
                    float4 a0 = *(const float4*)&sa[k * 68 + ty * 8];
                    float4 a1 = *(const float4*)&sa[k * 68 + ty * 8 + 4];
                    acc[0] += a0.x * bv; acc[1] += a0.y * bv;
                    acc[2] += a0.z * bv; acc[3] += a0.w * bv;
                    acc[4] += a1.x * bv; acc[5] += a1.y * bv;
                    acc[6] += a1.z * bv; acc[7] += a1.w * bv;
                }
                if (ch < 15) {
                    float* s = sAb + (buf ^ 1) * (32 * 68);
                    s[(q0 * 4 + 0) * 68 + b0] = n0.x; s[(q0 * 4 + 1) * 68 + b0] = n0.y;
                    s[(q0 * 4 + 2) * 68 + b0] = n0.z; s[(q0 * 4 + 3) * 68 + b0] = n0.w;
                    s[(q1 * 4 + 0) * 68 + b1] = n1.x; s[(q1 * 4 + 1) * 68 + b1] = n1.y;
                    s[(q1 * 4 + 2) * 68 + b1] = n1.z; s[(q1 * 4 + 3) * 68 + b1] = n1.w;
                    __syncthreads();
                }
            }
        }

        // stage gate tile: gsm[b][c]
#pragma unroll
        for (int i = 0; i < 8; i++) gsm[(ty * 8 + i) * 33 + tx] = acc[i];
        __syncthreads();

        // fused cell update: 512 (b,jj) pairs, 2 per thread
#pragma unroll
        for (int r = 0; r < 2; r++) {
            const int p = tid + r * 256;
            const int b = p >> 3, jj = p & 7;
            const float* pre = g_pre + (((size_t)dir * SS + tpos) * BB + b) * G4;
            float gi = pre[j0 + jj];
            float gf = pre[HH + j0 + jj];
            float gg = pre[2 * HH + j0 + jj];
            float go = pre[3 * HH + j0 + jj];
            float cp = 0.f;
            if (t > 0) {
                gi += gsm[b * 33 + jj];
                gf += gsm[b * 33 + 8 + jj];
                gg += gsm[b * 33 + 16 + jj];
                go += gsm[b * 33 + 24 + jj];
                cp = csm[b * 8 + jj];
            }
            float iv = 1.f / (1.f + expf(-gi));
            float fv = 1.f / (1.f + expf(-gf));
            float gv = tanhf(gg);
            float ov = 1.f / (1.f + expf(-go));
            float cn = fv * cp + iv * gv;
            csm[b * 8 + jj] = cn;
            g_h[((size_t)tpos * BB + b) * H2 + dirH + j0 + jj] = ov * tanhf(cn);
        }
        gbar();   // h(tpos) visible to all blocks before next step
    }
}

// ---- emissions (verified)
__global__ __launch_bounds__(256) void k_emisg(
    const float* __restrict__ Wout, const float* __restrict__ bout)
{
    int s = blockIdx.y;
    const float* A = g_h + (size_t)s * BB * H2;
    float* C = g_emis + (size_t)s * BB * TT;
    gemm_core(A, H2, Wout, H2, C, TT, bout, H2, 0, TT);
}

// ---- Viterbi (verified): one thread per batch, float output
__global__ __launch_bounds__(32) void k_vit_naive(
    const int* __restrict__ mask,
    const float* __restrict__ trans,
    const float* __restrict__ startT,
    const float* __restrict__ endT,
    float* __restrict__ out)
{
    const int b = blockIdx.x * 32 + threadIdx.x;
    if (b >= BB) return;

    float sc[TT];
    float ns[TT];
    unsigned char* hist = g_hist + (size_t)b * SS * TT;

    for (int n = 0; n < TT; n++)
        sc[n] = startT[n] + g_emis[(size_t)b * TT + n];

    for (int t = 1; t < SS; t++) {
        const int m = mask[b * SS + t];
        for (int n = 0; n < TT; n++) {
            float best = -3.4e38f; int arg = 0;
            for (int p = 0; p < TT; p++) {
                float v = sc[p] + trans[p * TT + n];
                if (v > best) { best = v; arg = p; }
            }
            ns[n] = best + g_emis[((size_t)t * BB + b) * TT + n];
            hist[(size_t)(t - 1) * TT + n] = m ? (unsigned char)arg
                                               : (unsigned char)0;
        }
        if (m)
            for (int n = 0; n < TT; n++) sc[n] = ns[n];
    }

    float best = -3.4e38f; int last = 0;
    for (int n = 0; n < TT; n++) {
        float v = sc[n] + endT[n];
        if (v > best) { best = v; last = n; }
    }

    out[b * SS + SS - 1] = (float)last;
    int cur = last;
    for (int t = SS - 2; t >= 0; t--) {
        cur = hist[(size_t)t * TT + cur];
        out[b * SS + t] = (float)cur;
    }
}

// =============================================================================
// Host (verified input mapper)
// =============================================================================
extern "C" void kernel_launch(void* const* d_in, const int* in_sizes, int n_in,
                              void* d_out, int out_size) {
    const long long SZ_X = (long long)BB * SS * DD;
    const long long SZ_MASK = (long long)BB * SS;
    const long long SZ_WIH = (long long)G4 * DD;
    const long long SZ_WHH = (long long)G4 * HH;
    const long long SZ_B4 = G4;
    const long long SZ_WOUT = (long long)TT * H2;
    const long long SZ_T21 = TT;
    const long long SZ_TR = (long long)TT * TT;

    int ix = -1, imask = -1, iwout = -1, itr = -1;
    int wih[2] = {-1, -1}, whh[2] = {-1, -1}, b4[2] = {-1, -1};
    int t21[3] = {-1, -1, -1};
    int nwih = 0, nwhh = 0, nb4 = 0, nt21 = 0;

    for (int scale_pass = 0; scale_pass < 2 && ix < 0; scale_pass++) {
        const long long mul = scale_pass ? 4 : 1;
        ix = imask = iwout = itr = -1;
        nwih = nwhh = nb4 = nt21 = 0;
        for (int i = 0; i < n_in; i++) {
            long long sz = (long long)in_sizes[i];
            if      (sz == SZ_X * mul)    ix = i;
            else if (sz == SZ_MASK * mul) imask = i;
            else if (sz == SZ_WOUT * mul) iwout = i;
            else if (sz == SZ_TR * mul)   itr = i;
            else if (sz == SZ_WIH * mul && nwih < 2) wih[nwih++] = i;
            else if (sz == SZ_WHH * mul && nwhh < 2) whh[nwhh++] = i;
            else if (sz == SZ_B4 * mul && nb4 < 2)   b4[nb4++] = i;
            else if (sz == SZ_T21 * mul && nt21 < 3) t21[nt21++] = i;
        }
    }

    const bool alpha = (ix == n_in - 1);
    const int iWihf = alpha ? wih[1] : wih[0];
    const int iWihb = alpha ? wih[0] : wih[1];
    const int iWhhf = alpha ? whh[1] : whh[0];
    const int iWhhb = alpha ? whh[0] : whh[1];
    const int ibf   = alpha ? b4[1] : b4[0];
    const int ibb   = alpha ? b4[0] : b4[1];
    const int ibout = t21[0];
    const int ist   = alpha ? t21[2] : t21[1];
    const int ien   = alpha ? t21[1] : t21[2];

    const float* x      = (const float*)d_in[ix];
    const int*   mask   = (const int*)  d_in[imask];
    const float* Wih_f  = (const float*)d_in[iWihf];
    const float* Whh_f  = (const float*)d_in[iWhhf];
    const float* b_f    = (const float*)d_in[ibf];
    const float* Wih_b  = (const float*)d_in[iWihb];
    const float* Whh_b  = (const float*)d_in[iWhhb];
    const float* b_b    = (const float*)d_in[ibb];
    const float* W_out  = (const float*)d_in[iwout];
    const float* b_out  = (const float*)d_in[ibout];
    const float* trans  = (const float*)d_in[itr];
    const float* startT = (const float*)d_in[ist];
    const float* endT   = (const float*)d_in[ien];
    float* out = (float*)d_out;

    // allow 95 KB dynamic smem for k_rec (no static guard; call every time)
    cudaFuncSetAttribute(k_rec, cudaFuncAttributeMaxDynamicSharedMemorySize,
                         SMEM_REC_BYTES);

    // 1) input projections (tiled GEMM)                        (1 node)
    k_pre<<<dim3(G4 / 64, SS * 2), 256>>>(x, Wih_f, b_f, Wih_b, b_b);
    // 2) recurrence: persistent, Whh resident in smem          (1 node)
    k_rec<<<NBLK, 256, SMEM_REC_BYTES>>>(Whh_f, Whh_b);
    // 3) emissions (tiled GEMM)                                (1 node)
    k_emisg<<<dim3(1, SS), 256>>>(W_out, b_out);
    // 4) viterbi (float output)                                (1 node)
    k_vit_naive<<<2, 32>>>(mask, trans, startT, endT, out);
    // total 4 graph nodes.
}

// round 13
// speedup vs baseline: 35.7092x; 1.1725x over previous
#include <cuda_runtime.h>
#include <cuda_bf16.h>

#define BB 64      // batch
#define SS 512     // seq len
#define DD 768     // input dim
#define HH 512     // hidden
#define TT 21      // tags
#define G4 2048    // 4*H
#define H2 1024    // 2*H
#define NBLK_DIR 64   // persistent blocks per direction (barrier group)

// ---------------- scratch (device globals; no allocation allowed) ------------
__device__ float g_pre[(size_t)2 * SS * BB * G4];   // [dir][s][b][4H]
__device__ float g_h[(size_t)SS * BB * H2];          // [s][b][2H] (fwd | bwd)
__device__ float g_emis[(size_t)SS * BB * TT];       // [s][b][T]
__device__ unsigned char g_hist[(size_t)BB * SS * TT]; // viterbi backtrace

// per-direction grid barrier state
__device__ unsigned g_cnt[2] = {0, 0};
__device__ volatile unsigned g_gend[2] = {0, 0};

__device__ __forceinline__ void gbar_dir(int dir) {
    __syncthreads();
    if (threadIdx.x == 0) {
        __threadfence();
        unsigned my = g_gend[dir];
        if (atomicAdd(&g_cnt[dir], 1) == NBLK_DIR - 1) {
            g_cnt[dir] = 0;
            __threadfence();
            g_gend[dir] = my + 1;
        } else {
            while (g_gend[dir] == my) { }
        }
        __threadfence();
    }
    __syncthreads();
}

__device__ __forceinline__ float4 ldcg4(const float* p) {
    return __ldcg((const float4*)p);
}

// =============================================================================
// 1) Pre-GEMM v2: pre[dir][s][b][n] = x[b][s][:].Wih[n][:] + bias[n]
//    M=32768 (m = b*512+s), N=2048, K=768. 128x128 tile, 8x8 micro, float4,
//    double-buffered. grid (16, 256, 2), 256 threads, 2 blocks/SM.
// =============================================================================
__global__ __launch_bounds__(256, 2) void k_pre2(
    const float* __restrict__ x,
    const float* __restrict__ Wf, const float* __restrict__ bf,
    const float* __restrict__ Wb, const float* __restrict__ bbv)
{
    const int dir = blockIdx.z;
    const float* __restrict__ W    = dir ? Wb : Wf;
    const float* __restrict__ bias = dir ? bbv : bf;
    const int m0 = blockIdx.y * 128;
    const int n0 = blockIdx.x * 128;

    __shared__ __align__(16) float As[2][8][128];
    __shared__ __align__(16) float Bs[2][8][128];

    const int tid = threadIdx.x;
    const int tx = tid & 15;        // n micro (8 cols)
    const int ty = tid >> 4;        // m micro (8 rows)
    const int lrow = tid >> 1;      // 0..127
    const int lk   = (tid & 1) * 4; // 0 or 4

    const float* Aptr = x + (size_t)(m0 + lrow) * DD + lk;
    const float* Bptr = W + (size_t)(n0 + lrow) * DD + lk;

    float acc[8][8];
#pragma unroll
    for (int i = 0; i < 8; i++)
#pragma unroll
        for (int j = 0; j < 8; j++) acc[i][j] = 0.f;

    // prologue: chunk 0
    {
        float4 av = *(const float4*)Aptr;
        float4 bv = *(const float4*)Bptr;
        As[0][lk + 0][lrow] = av.x; As[0][lk + 1][lrow] = av.y;
        As[0][lk + 2][lrow] = av.z; As[0][lk + 3][lrow] = av.w;
        Bs[0][lk + 0][lrow] = bv.x; Bs[0][lk + 1][lrow] = bv.y;
        Bs[0][lk + 2][lrow] = bv.z; Bs[0][lk + 3][lrow] = bv.w;
    }
    __syncthreads();

#pragma unroll 1
    for (int c = 0; c < 96; c++) {          // 768 / 8
        const int cur = c & 1;
        float4 nav, nbv;
        if (c < 95) {
            nav = *(const float4*)(Aptr + (c + 1) * 8);
            nbv = *(const float4*)(Bptr + (c + 1) * 8);
        }
#pragma unroll
        for (int k = 0; k < 8; k++) {
            float4 a0 = *(const float4*)&As[cur][k][ty * 8];
            float4 a1 = *(const float4*)&As[cur][k][ty * 8 + 4];
            float4 b0 = *(const float4*)&Bs[cur][k][tx * 8];
            float4 b1 = *(const float4*)&Bs[cur][k][tx * 8 + 4];
            float aa[8]  = {a0.x, a0.y, a0.z, a0.w, a1.x, a1.y, a1.z, a1.w};
            float bb2[8] = {b0.x, b0.y, b0.z, b0.w, b1.x, b1.y, b1.z, b1.w};
#pragma unroll
            for (int i = 0; i < 8; i++)
#pragma unroll
                for (int j = 0; j < 8; j++) acc[i][j] += aa[i] * bb2[j];
        }
        if (c < 95) {
            const int nxt = cur ^ 1;
            As[nxt][lk + 0][lrow] = nav.x; As[nxt][lk + 1][lrow] = nav.y;
            As[nxt][lk + 2][lrow] = nav.z; As[nxt][lk + 3][lrow] = nav.w;
            Bs[nxt][lk + 0][lrow] = nbv.x; Bs[nxt][lk + 1][lrow] = nbv.y;
            Bs[nxt][lk + 2][lrow] = nbv.z; Bs[nxt][lk + 3][lrow] = nbv.w;
        }
        __syncthreads();
    }

#pragma unroll
    for (int i = 0; i < 8; i++) {
        const int m = m0 + ty * 8 + i;
        const int b = m >> 9, s = m & 511;
        float* Crow = g_pre + (((size_t)dir * SS + s) * BB + b) * G4;
#pragma unroll
        for (int j = 0; j < 8; j++) {
            const int n = n0 + tx * 8 + j;
            Crow[n] = acc[i][j] + bias[n];
        }
    }
}

// =============================================================================
// 2) Persistent recurrence (R12-verified), now with PER-DIRECTION barriers:
//    fwd and bwd scans never exchange data, so each 64-block group syncs
//    independently (smaller fan-in, decoupled jitter).
// =============================================================================
#define SMEM_REC_FLOATS (512 * 33 + 2 * 32 * 68 + 64 * 33 + 64 * 8)
#define SMEM_REC_BYTES  (SMEM_REC_FLOATS * 4)

__global__ __launch_bounds__(256) void k_rec(
    const float* __restrict__ Whf, const float* __restrict__ Whb)
{
    extern __shared__ __align__(16) float sm[];
    float* Wsm = sm;                        // [k][c]  512*33
    float* sAb = Wsm + 512 * 33;            // [2][32][68]
    float* gsm = sAb + 2 * 32 * 68;         // [b][c]  64*33
    float* csm = gsm + 64 * 33;             // [b][jj] 64*8

    const int bid = blockIdx.x;
    const int dir = bid >> 6;
    const int j0  = (bid & 63) * 8;
    const int tid = threadIdx.x;
    const int tx  = tid & 31;               // col c
    const int ty  = tid >> 5;               // m-group (8 rows)
    const int dirH = dir * HH;
    const float* __restrict__ Whh = dir ? Whb : Whf;

    // ---- load Whh slice once: Wsm[k][c], c = gate*8 + jj ----
    {
        const int c = tid >> 3;                       // 0..31
        const int n = (c >> 3) * HH + j0 + (c & 7);   // weight row
        const float* wrow = Whh + (size_t)n * HH;
        const int kq = (tid & 7) * 16;
#pragma unroll
        for (int q = 0; q < 16; q++) {
            float4 v = *(const float4*)(wrow + (size_t)(kq + q) * 4);
            const int k = (kq + q) * 4;
            Wsm[(k + 0) * 33 + c] = v.x;
            Wsm[(k + 1) * 33 + c] = v.y;
            Wsm[(k + 2) * 33 + c] = v.z;
            Wsm[(k + 3) * 33 + c] = v.w;
        }
    }
    __syncthreads();

    const int b0 = (tid * 2) >> 3,     q0 = (tid * 2) & 7;
    const int b1 = (tid * 2 + 1) >> 3, q1 = (tid * 2 + 1) & 7;

    for (int t = 0; t < SS; t++) {
        const int tpos = dir ? (SS - 1 - t) : t;
        float acc[8];
#pragma unroll
        for (int i = 0; i < 8; i++) acc[i] = 0.f;

        if (t > 0) {
            const int tprev = dir ? (tpos + 1) : (tpos - 1);
            const float* Ab = g_h + (size_t)tprev * BB * H2 + dirH;
            const float* ap0 = Ab + (size_t)b0 * H2 + q0 * 4;
            const float* ap1 = Ab + (size_t)b1 * H2 + q1 * 4;

            float4 r0 = ldcg4(ap0);
            float4 r1 = ldcg4(ap1);
            {
                float* s = sAb;
                s[(q0 * 4 + 0) * 68 + b0] = r0.x; s[(q0 * 4 + 1) * 68 + b0] = r0.y;
                s[(q0 * 4 + 2) * 68 + b0] = r0.z; s[(q0 * 4 + 3) * 68 + b0] = r0.w;
                s[(q1 * 4 + 0) * 68 + b1] = r1.x; s[(q1 * 4 + 1) * 68 + b1] = r1.y;
                s[(q1 * 4 + 2) * 68 + b1] = r1.z; s[(q1 * 4 + 3) * 68 + b1] = r1.w;
            }
            __syncthreads();

#pragma unroll 1
            for (int ch = 0; ch < 16; ch++) {
                const int buf = ch & 1;
                float4 n0, n1;
                if (ch < 15) {
                    n0 = ldcg4(ap0 + (ch + 1) * 32);
                    n1 = ldcg4(ap1 + (ch + 1) * 32);
                }
                const float* sa = sAb + buf * (32 * 68);
                const float* wk = Wsm + (ch * 32) * 33 + tx;
#pragma unroll
                for (int k = 0; k < 32; k++) {
                    const float bv = wk[k * 33];
                    float4 a0 = *(const float4*)&sa[k * 68 + ty * 8];
                    float4 a1 = *(const float4*)&sa[k * 68 + ty * 8 + 4];
                    acc[0] += a0.x * bv; acc[1] += a0.y * bv;
                    acc[2] += a0.z * bv; acc[3] += a0.w * bv;
                    acc[4] += a1.x * bv; acc[5] += a1.y * bv;
                    acc[6] += a1.z * bv; acc[7] += a1.w * bv;
                }
                if (ch < 15) {
                    float* s = sAb + (buf ^ 1) * (32 * 68);
                    s[(q0 * 4 + 0) * 68 + b0] = n0.x; s[(q0 * 4 + 1) * 68 + b0] = n0.y;
                    s[(q0 * 4 + 2) * 68 + b0] = n0.z; s[(q0 * 4 + 3) * 68 + b0] = n0.w;
                    s[(q1 * 4 + 0) * 68 + b1] = n1.x; s[(q1 * 4 + 1) * 68 + b1] = n1.y;
                    s[(q1 * 4 + 2) * 68 + b1] = n1.z; s[(q1 * 4 + 3) * 68 + b1] = n1.w;
                    __syncthreads();
                }
            }
        }

#pragma unroll
        for (int i = 0; i < 8; i++) gsm[(ty * 8 + i) * 33 + tx] = acc[i];
        __syncthreads();

#pragma unroll
        for (int r = 0; r < 2; r++) {
            const int p = tid + r * 256;
            const int b = p >> 3, jj = p & 7;
            const float* pre = g_pre + (((size_t)dir * SS + tpos) * BB + b) * G4;
            float gi = pre[j0 + jj];
            float gf = pre[HH + j0 + jj];
            float gg = pre[2 * HH + j0 + jj];
            float go = pre[3 * HH + j0 + jj];
            float cp = 0.f;
            if (t > 0) {
                gi += gsm[b * 33 + jj];
                gf += gsm[b * 33 + 8 + jj];
                gg += gsm[b * 33 + 16 + jj];
                go += gsm[b * 33 + 24 + jj];
                cp = csm[b * 8 + jj];
            }
            float iv = 1.f / (1.f + expf(-gi));
            float fv = 1.f / (1.f + expf(-gf));
            float gv = tanhf(gg);
            float ov = 1.f / (1.f + expf(-go));
            float cn = fv * cp + iv * gv;
            csm[b * 8 + jj] = cn;
            g_h[((size_t)tpos * BB + b) * H2 + dirH + j0 + jj] = ov * tanhf(cn);
        }
        gbar_dir(dir);   // sync only this direction's 64 blocks
    }
}

// =============================================================================
// 3) Emissions (verified scalar GEMM core, unchanged)
// =============================================================================
__device__ __forceinline__ void gemm_core(
    const float* __restrict__ A, int lda,
    const float* __restrict__ Bw, int ldb,
    float* __restrict__ C, int ldc,
    const float* __restrict__ bias,
    int K, int n0, int N)
{
    __shared__ float sA[16][65];
    __shared__ float sB[16][65];

    const int tid = threadIdx.x;
    const int tx = tid & 15;
    const int ty = tid >> 4;

    float acc[4][4];
#pragma unroll
    for (int i = 0; i < 4; i++)
#pragma unroll
        for (int j = 0; j < 4; j++) acc[i][j] = 0.f;

    for (int k0 = 0; k0 < K; k0 += 16) {
#pragma unroll
        for (int r = 0; r < 4; r++) {
            int idx = tid + r * 256;
            int k  = idx & 15;
            int mn = idx >> 4;
            sA[k][mn] = A[(size_t)mn * lda + k0 + k];
            int n = n0 + mn;
            sB[k][mn] = (n < N) ? Bw[(size_t)n * ldb + k0 + k] : 0.f;
        }
        __syncthreads();
#pragma unroll
        for (int k = 0; k < 16; k++) {
            float a0 = sA[k][ty * 4 + 0];
            float a1 = sA[k][ty * 4 + 1];
            float a2 = sA[k][ty * 4 + 2];
            float a3 = sA[k][ty * 4 + 3];
            float b0 = sB[k][tx * 4 + 0];
            float b1 = sB[k][tx * 4 + 1];
            float b2 = sB[k][tx * 4 + 2];
            float b3 = sB[k][tx * 4 + 3];
            acc[0][0] += a0 * b0; acc[0][1] += a0 * b1; acc[0][2] += a0 * b2; acc[0][3] += a0 * b3;
            acc[1][0] += a1 * b0; acc[1][1] += a1 * b1; acc[1][2] += a1 * b2; acc[1][3] += a1 * b3;
            acc[2][0] += a2 * b0; acc[2][1] += a2 * b1; acc[2][2] += a2 * b2; acc[2][3] += a2 * b3;
            acc[3][0] += a3 * b0; acc[3][1] += a3 * b1; acc[3][2] += a3 * b2; acc[3][3] += a3 * b3;
        }
        __syncthreads();
    }

#pragma unroll
    for (int i = 0; i < 4; i++) {
        int m = ty * 4 + i;
#pragma unroll
        for (int j = 0; j < 4; j++) {
            int n = n0 + tx * 4 + j;
            if (n < N)
                C[(size_t)m * ldc + n] = acc[i][j] + (bias ? bias[n] : 0.f);
        }
    }
}

__global__ __launch_bounds__(256) void k_emisg(
    const float* __restrict__ Wout, const float* __restrict__ bout)
{
    int s = blockIdx.y;
    const float* A = g_h + (size_t)s * BB * H2;
    float* C = g_emis + (size_t)s * BB * TT;
    gemm_core(A, H2, Wout, H2, C, TT, bout, H2, 0, TT);
}

// ---- Viterbi (verified): one thread per batch, float output
__global__ __launch_bounds__(32) void k_vit_naive(
    const int* __restrict__ mask,
    const float* __restrict__ trans,
    const float* __restrict__ startT,
    const float* __restrict__ endT,
    float* __restrict__ out)
{
    const int b = blockIdx.x * 32 + threadIdx.x;
    if (b >= BB) return;

    float sc[TT];
    float ns[TT];
    unsigned char* hist = g_hist + (size_t)b * SS * TT;

    for (int n = 0; n < TT; n++)
        sc[n] = startT[n] + g_emis[(size_t)b * TT + n];

    for (int t = 1; t < SS; t++) {
        const int m = mask[b * SS + t];
        for (int n = 0; n < TT; n++) {
            float best = -3.4e38f; int arg = 0;
            for (int p = 0; p < TT; p++) {
                float v = sc[p] + trans[p * TT + n];
                if (v > best) { best = v; arg = p; }
            }
            ns[n] = best + g_emis[((size_t)t * BB + b) * TT + n];
            hist[(size_t)(t - 1) * TT + n] = m ? (unsigned char)arg
                                               : (unsigned char)0;
        }
        if (m)
            for (int n = 0; n < TT; n++) sc[n] = ns[n];
    }

    float best = -3.4e38f; int last = 0;
    for (int n = 0; n < TT; n++) {
        float v = sc[n] + endT[n];
        if (v > best) { best = v; last = n; }
    }

    out[b * SS + SS - 1] = (float)last;
    int cur = last;
    for (int t = SS - 2; t >= 0; t--) {
        cur = hist[(size_t)t * TT + cur];
        out[b * SS + t] = (float)cur;
    }
}

// =============================================================================
// Host (verified input mapper)
// =============================================================================
extern "C" void kernel_launch(void* const* d_in, const int* in_sizes, int n_in,
                              void* d_out, int out_size) {
    const long long SZ_X = (long long)BB * SS * DD;
    const long long SZ_MASK = (long long)BB * SS;
    const long long SZ_WIH = (long long)G4 * DD;
    const long long SZ_WHH = (long long)G4 * HH;
    const long long SZ_B4 = G4;
    const long long SZ_WOUT = (long long)TT * H2;
    const long long SZ_T21 = TT;
    const long long SZ_TR = (long long)TT * TT;

    int ix = -1, imask = -1, iwout = -1, itr = -1;
    int wih[2] = {-1, -1}, whh[2] = {-1, -1}, b4[2] = {-1, -1};
    int t21[3] = {-1, -1, -1};
    int nwih = 0, nwhh = 0, nb4 = 0, nt21 = 0;

    for (int scale_pass = 0; scale_pass < 2 && ix < 0; scale_pass++) {
        const long long mul = scale_pass ? 4 : 1;
        ix = imask = iwout = itr = -1;
        nwih = nwhh = nb4 = nt21 = 0;
        for (int i = 0; i < n_in; i++) {
            long long sz = (long long)in_sizes[i];
            if      (sz == SZ_X * mul)    ix = i;
            else if (sz == SZ_MASK * mul) imask = i;
            else if (sz == SZ_WOUT * mul) iwout = i;
            else if (sz == SZ_TR * mul)   itr = i;
            else if (sz == SZ_WIH * mul && nwih < 2) wih[nwih++] = i;
            else if (sz == SZ_WHH * mul && nwhh < 2) whh[nwhh++] = i;
            else if (sz == SZ_B4 * mul && nb4 < 2)   b4[nb4++] = i;
            else if (sz == SZ_T21 * mul && nt21 < 3) t21[nt21++] = i;
        }
    }

    const bool alpha = (ix == n_in - 1);
    const int iWihf = alpha ? wih[1] : wih[0];
    const int iWihb = alpha ? wih[0] : wih[1];
    const int iWhhf = alpha ? whh[1] : whh[0];
    const int iWhhb = alpha ? whh[0] : whh[1];
    const int ibf   = alpha ? b4[1] : b4[0];
    const int ibb   = alpha ? b4[0] : b4[1];
    const int ibout = t21[0];
    const int ist   = alpha ? t21[2] : t21[1];
    const int ien   = alpha ? t21[1] : t21[2];

    const float* x      = (const float*)d_in[ix];
    const int*   mask   = (const int*)  d_in[imask];
    const float* Wih_f  = (const float*)d_in[iWihf];
    const float* Whh_f  = (const float*)d_in[iWhhf];
    const float* b_f    = (const float*)d_in[ibf];
    const float* Wih_b  = (const float*)d_in[iWihb];
    const float* Whh_b  = (const float*)d_in[iWhhb];
    const float* b_b    = (const float*)d_in[ibb];
    const float* W_out  = (const float*)d_in[iwout];
    const float* b_out  = (const float*)d_in[ibout];
    const float* trans  = (const float*)d_in[itr];
    const float* startT = (const float*)d_in[ist];
    const float* endT   = (const float*)d_in[ien];
    float* out = (float*)d_out;

    cudaFuncSetAttribute(k_rec, cudaFuncAttributeMaxDynamicSharedMemorySize,
                         SMEM_REC_BYTES);

    // 1) input projections (float4 128x128 GEMM)               (1 node)
    k_pre2<<<dim3(G4 / 128, 256, 2), 256>>>(x, Wih_f, b_f, Wih_b, b_b);
    // 2) recurrence: persistent, per-direction barriers        (1 node)
    k_rec<<<2 * NBLK_DIR, 256, SMEM_REC_BYTES>>>(Whh_f, Whh_b);
    // 3) emissions                                             (1 node)
    k_emisg<<<dim3(1, SS), 256>>>(W_out, b_out);
    // 4) viterbi (float output)                                (1 node)
    k_vit_naive<<<2, 32>>>(mask, trans, startT, endT, out);
    // total 4 graph nodes.
}

// round 14
// speedup vs baseline: 41.4822x; 1.1617x over previous
#include <cuda_runtime.h>
#include <cuda_bf16.h>

#define BB 64      // batch
#define SS 512     // seq len
#define DD 768     // input dim
#define HH 512     // hidden
#define TT 21      // tags
#define G4 2048    // 4*H
#define H2 1024    // 2*H
#define NBLK_DIR 64   // persistent blocks per direction (barrier group)

// ---------------- scratch (device globals; no allocation allowed) ------------
__device__ float g_pre[(size_t)2 * SS * BB * G4];   // [dir][s][b][4H]
__device__ float g_h[(size_t)SS * BB * H2];          // [s][b][2H] (fwd | bwd)
__device__ float g_hT[(size_t)SS * H2 * BB];         // [s][k(2H)][b]  transposed mirror
__device__ float g_emis[(size_t)SS * BB * TT];       // [s][b][T]
__device__ unsigned char g_hist[(size_t)BB * SS * TT]; // viterbi backtrace

// per-direction grid barrier state
__device__ unsigned g_cnt[2] = {0, 0};
__device__ volatile unsigned g_gend[2] = {0, 0};

__device__ __forceinline__ void gbar_dir(int dir) {
    __syncthreads();
    if (threadIdx.x == 0) {
        __threadfence();
        unsigned my = g_gend[dir];
        if (atomicAdd(&g_cnt[dir], 1) == NBLK_DIR - 1) {
            g_cnt[dir] = 0;
            __threadfence();
            g_gend[dir] = my + 1;
        } else {
            while (g_gend[dir] == my) { }
        }
        __threadfence();
    }
    __syncthreads();
}

__device__ __forceinline__ float4 ldcg4(const float* p) {
    return __ldcg((const float4*)p);
}

// =============================================================================
// 1) Pre-GEMM (R13-verified): 128x128 tile, 8x8 micro, float4, double-buffered
// =============================================================================
__global__ __launch_bounds__(256, 2) void k_pre2(
    const float* __restrict__ x,
    const float* __restrict__ Wf, const float* __restrict__ bf,
    const float* __restrict__ Wb, const float* __restrict__ bbv)
{
    const int dir = blockIdx.z;
    const float* __restrict__ W    = dir ? Wb : Wf;
    const float* __restrict__ bias = dir ? bbv : bf;
    const int m0 = blockIdx.y * 128;
    const int n0 = blockIdx.x * 128;

    __shared__ __align__(16) float As[2][8][128];
    __shared__ __align__(16) float Bs[2][8][128];

    const int tid = threadIdx.x;
    const int tx = tid & 15;
    const int ty = tid >> 4;
    const int lrow = tid >> 1;
    const int lk   = (tid & 1) * 4;

    const float* Aptr = x + (size_t)(m0 + lrow) * DD + lk;
    const float* Bptr = W + (size_t)(n0 + lrow) * DD + lk;

    float acc[8][8];
#pragma unroll
    for (int i = 0; i < 8; i++)
#pragma unroll
        for (int j = 0; j < 8; j++) acc[i][j] = 0.f;

    {
        float4 av = *(const float4*)Aptr;
        float4 bv = *(const float4*)Bptr;
        As[0][lk + 0][lrow] = av.x; As[0][lk + 1][lrow] = av.y;
        As[0][lk + 2][lrow] = av.z; As[0][lk + 3][lrow] = av.w;
        Bs[0][lk + 0][lrow] = bv.x; Bs[0][lk + 1][lrow] = bv.y;
        Bs[0][lk + 2][lrow] = bv.z; Bs[0][lk + 3][lrow] = bv.w;
    }
    __syncthreads();

#pragma unroll 1
    for (int c = 0; c < 96; c++) {
        const int cur = c & 1;
        float4 nav, nbv;
        if (c < 95) {
            nav = *(const float4*)(Aptr + (c + 1) * 8);
            nbv = *(const float4*)(Bptr + (c + 1) * 8);
        }
#pragma unroll
        for (int k = 0; k < 8; k++) {
            float4 a0 = *(const float4*)&As[cur][k][ty * 8];
            float4 a1 = *(const float4*)&As[cur][k][ty * 8 + 4];
            float4 b0 = *(const float4*)&Bs[cur][k][tx * 8];
            float4 b1 = *(const float4*)&Bs[cur][k][tx * 8 + 4];
            float aa[8]  = {a0.x, a0.y, a0.z, a0.w, a1.x, a1.y, a1.z, a1.w};
            float bb2[8] = {b0.x, b0.y, b0.z, b0.w, b1.x, b1.y, b1.z, b1.w};
#pragma unroll
            for (int i = 0; i < 8; i++)
#pragma unroll
                for (int j = 0; j < 8; j++) acc[i][j] += aa[i] * bb2[j];
        }
        if (c < 95) {
            const int nxt = cur ^ 1;
            As[nxt][lk + 0][lrow] = nav.x; As[nxt][lk + 1][lrow] = nav.y;
            As[nxt][lk + 2][lrow] = nav.z; As[nxt][lk + 3][lrow] = nav.w;
            Bs[nxt][lk + 0][lrow] = nbv.x; Bs[nxt][lk + 1][lrow] = nbv.y;
            Bs[nxt][lk + 2][lrow] = nbv.z; Bs[nxt][lk + 3][lrow] = nbv.w;
        }
        __syncthreads();
    }

#pragma unroll
    for (int i = 0; i < 8; i++) {
        const int m = m0 + ty * 8 + i;
        const int b = m >> 9, s = m & 511;
        float* Crow = g_pre + (((size_t)dir * SS + s) * BB + b) * G4;
#pragma unroll
        for (int j = 0; j < 8; j++) {
            const int n = n0 + tx * 8 + j;
            Crow[n] = acc[i][j] + bias[n];
        }
    }
}

// =============================================================================
// 2) Persistent recurrence v3: transpose-free staging via g_hT mirror.
//    128 blocks (dir = bid>>6, j0 = (bid&63)*8), 512 threads, split-K halves.
//    Per step: contiguous 128KB copy g_hT->smem (coalesced, conflict-free),
//    one FMA phase (8 FFMA + 3 LDS per k per thread), gsm[2] combine,
//    fused cell update writes BOTH g_h and g_hT, per-dir grid barrier.
// =============================================================================
#define RSM_W  (512 * 32)          // Wsm [k][c]
#define RSM_H  (512 * 64)          // hs  [k][b]  (contiguous, stride 64)
#define RSM_G  (2 * 64 * 33)       // gsm [half][b][c]
#define RSM_C  (64 * 8)            // csm [b][jj]
#define SMEM_REC_BYTES ((RSM_W + RSM_H + RSM_G + RSM_C) * 4)

__global__ __launch_bounds__(512) void k_rec(
    const float* __restrict__ Whf, const float* __restrict__ Whb)
{
    extern __shared__ __align__(16) float sm[];
    float* Wsm = sm;                 // [k][32]
    float* hs  = Wsm + RSM_W;        // [k][64]
    float* gsm = hs + RSM_H;         // [2][64][33]
    float* csm = gsm + RSM_G;        // [64][8]

    const int bid  = blockIdx.x;
    const int dir  = bid >> 6;
    const int j0   = (bid & 63) * 8;
    const int tid  = threadIdx.x;            // 0..511
    const int tx   = tid & 31;               // col c = gate*8 + jj
    const int ty   = (tid >> 5) & 7;         // m-group (8 batches)
    const int half = tid >> 8;               // k-half 0/1
    const int dirH = dir * HH;
    const float* __restrict__ Whh = dir ? Whb : Whf;

    // ---- load Whh slice once: Wsm[k][c] ----
    {
        const int c = tid >> 4;                       // 0..31
        const int n = (c >> 3) * HH + j0 + (c & 7);   // weight row
        const float* wrow = Whh + (size_t)n * HH;
        const int ks = (tid & 15) * 32;               // 32 consecutive k
#pragma unroll
        for (int q = 0; q < 8; q++) {
            float4 v = *(const float4*)(wrow + ks + q * 4);
            Wsm[(ks + q * 4 + 0) * 32 + c] = v.x;
            Wsm[(ks + q * 4 + 1) * 32 + c] = v.y;
            Wsm[(ks + q * 4 + 2) * 32 + c] = v.z;
            Wsm[(ks + q * 4 + 3) * 32 + c] = v.w;
        }
    }
    __syncthreads();

    for (int t = 0; t < SS; t++) {
        const int tpos = dir ? (SS - 1 - t) : t;

        if (t > 0) {
            // ---- staging: contiguous copy of h^T slice (512 k x 64 b) ----
            const int tprev = dir ? (tpos + 1) : (tpos - 1);
            const float* src = g_hT + ((size_t)tprev * H2 + dirH) * 64;
#pragma unroll
            for (int j2 = 0; j2 < 16; j2++) {
                const int f = tid + 512 * j2;        // float4 index 0..8191
                float4 v = ldcg4(src + (size_t)f * 4);
                *(float4*)(hs + (size_t)f * 4) = v;
            }
            __syncthreads();

            // ---- FMA phase: this thread's k-half ----
            float acc[8];
#pragma unroll
            for (int i = 0; i < 8; i++) acc[i] = 0.f;
            const int kbase = half * 256;
#pragma unroll 1
            for (int kc = 0; kc < 8; kc++) {
#pragma unroll
                for (int kk = 0; kk < 32; kk++) {
                    const int k = kbase + kc * 32 + kk;
                    const float bv = Wsm[k * 32 + tx];
                    float4 a0 = *(const float4*)&hs[k * 64 + ty * 8];
                    float4 a1 = *(const float4*)&hs[k * 64 + ty * 8 + 4];
                    acc[0] += a0.x * bv; acc[1] += a0.y * bv;
                    acc[2] += a0.z * bv; acc[3] += a0.w * bv;
                    acc[4] += a1.x * bv; acc[5] += a1.y * bv;
                    acc[6] += a1.z * bv; acc[7] += a1.w * bv;
                }
            }
#pragma unroll
            for (int i = 0; i < 8; i++)
                gsm[half * (64 * 33) + (ty * 8 + i) * 33 + tx] = acc[i];
        }
        __syncthreads();

        // ---- fused cell update: 512 (b,jj) pairs, 1 per thread ----
        {
            const int b  = tid >> 3;
            const int jj = tid & 7;
            const float* pre = g_pre + (((size_t)dir * SS + tpos) * BB + b) * G4;
            float gi = pre[j0 + jj];
            float gf = pre[HH + j0 + jj];
            float gg = pre[2 * HH + j0 + jj];
            float go = pre[3 * HH + j0 + jj];
            float cp = 0.f;
            if (t > 0) {
                const int g0 = b * 33;
                gi += gsm[g0 + jj]           + gsm[64 * 33 + g0 + jj];
                gf += gsm[g0 + 8 + jj]       + gsm[64 * 33 + g0 + 8 + jj];
                gg += gsm[g0 + 16 + jj]      + gsm[64 * 33 + g0 + 16 + jj];
                go += gsm[g0 + 24 + jj]      + gsm[64 * 33 + g0 + 24 + jj];
                cp = csm[b * 8 + jj];
            }
            float iv = 1.f / (1.f + expf(-gi));
            float fv = 1.f / (1.f + expf(-gf));
            float gv = tanhf(gg);
            float ov = 1.f / (1.f + expf(-go));
            float cn = fv * cp + iv * gv;
            csm[b * 8 + jj] = cn;
            float hv = ov * tanhf(cn);
            g_h[((size_t)tpos * BB + b) * H2 + dirH + j0 + jj] = hv;
            g_hT[((size_t)tpos * H2 + dirH + j0 + jj) * 64 + b] = hv;
        }
        gbar_dir(dir);   // h(tpos) + hT(tpos) visible before next step
    }
}

// =============================================================================
// 3) Emissions (verified scalar GEMM core, unchanged)
// =============================================================================
__device__ __forceinline__ void gemm_core(
    const float* __restrict__ A, int lda,
    const float* __restrict__ Bw, int ldb,
    float* __restrict__ C, int ldc,
    const float* __restrict__ bias,
    int K, int n0, int N)
{
    __shared__ float sA[16][65];
    __shared__ float sB[16][65];

    const int tid = threadIdx.x;
    const int tx = tid & 15;
    const int ty = tid >> 4;

    float acc[4][4];
#pragma unroll
    for (int i = 0; i < 4; i++)
#pragma unroll
        for (int j = 0; j < 4; j++) acc[i][j] = 0.f;

    for (int k0 = 0; k0 < K; k0 += 16) {
#pragma unroll
        for (int r = 0; r < 4; r++) {
            int idx = tid + r * 256;
            int k  = idx & 15;
            int mn = idx >> 4;
            sA[k][mn] = A[(size_t)mn * lda + k0 + k];
            int n = n0 + mn;
            sB[k][mn] = (n < N) ? Bw[(size_t)n * ldb + k0 + k] : 0.f;
        }
        __syncthreads();
#pragma unroll
        for (int k = 0; k < 16; k++) {
            float a0 = sA[k][ty * 4 + 0];
            float a1 = sA[k][ty * 4 + 1];
            float a2 = sA[k][ty * 4 + 2];
            float a3 = sA[k][ty * 4 + 3];
            float b0 = sB[k][tx * 4 + 0];
            float b1 = sB[k][tx * 4 + 1];
            float b2 = sB[k][tx * 4 + 2];
            float b3 = sB[k][tx * 4 + 3];
            acc[0][0] += a0 * b0; acc[0][1] += a0 * b1; acc[0][2] += a0 * b2; acc[0][3] += a0 * b3;
            acc[1][0] += a1 * b0; acc[1][1] += a1 * b1; acc[1][2] += a1 * b2; acc[1][3] += a1 * b3;
            acc[2][0] += a2 * b0; acc[2][1] += a2 * b1; acc[2][2] += a2 * b2; acc[2][3] += a2 * b3;
            acc[3][0] += a3 * b0; acc[3][1] += a3 * b1; acc[3][2] += a3 * b2; acc[3][3] += a3 * b3;
        }
        __syncthreads();
    }

#pragma unroll
    for (int i = 0; i < 4; i++) {
        int m = ty * 4 + i;
#pragma unroll
        for (int j = 0; j < 4; j++) {
            int n = n0 + tx * 4 + j;
            if (n < N)
                C[(size_t)m * ldc + n] = acc[i][j] + (bias ? bias[n] : 0.f);
        }
    }
}

__global__ __launch_bounds__(256) void k_emisg(
    const float* __restrict__ Wout, const float* __restrict__ bout)
{
    int s = blockIdx.y;
    const float* A = g_h + (size_t)s * BB * H2;
    float* C = g_emis + (size_t)s * BB * TT;
    gemm_core(A, H2, Wout, H2, C, TT, bout, H2, 0, TT);
}

// ---- Viterbi (verified): one thread per batch, float output
__global__ __launch_bounds__(32) void k_vit_naive(
    const int* __restrict__ mask,
    const float* __restrict__ trans,
    const float* __restrict__ startT,
    const float* __restrict__ endT,
    float* __restrict__ out)
{
    const int b = blockIdx.x * 32 + threadIdx.x;
    if (b >= BB) return;

    float sc[TT];
    float ns[TT];
    unsigned char* hist = g_hist + (size_t)b * SS * TT;

    for (int n = 0; n < TT; n++)
        sc[n] = startT[n] + g_emis[(size_t)b * TT + n];

    for (int t = 1; t < SS; t++) {
        const int m = mask[b * SS + t];
        for (int n = 0; n < TT; n++) {
            float best = -3.4e38f; int arg = 0;
            for (int p = 0; p < TT; p++) {
                float v = sc[p] + trans[p * TT + n];
                if (v > best) { best = v; arg = p; }
            }
            ns[n] = best + g_emis[((size_t)t * BB + b) * TT + n];
            hist[(size_t)(t - 1) * TT + n] = m ? (unsigned char)arg
                                               : (unsigned char)0;
        }
        if (m)
            for (int n = 0; n < TT; n++) sc[n] = ns[n];
    }

    float best = -3.4e38f; int last = 0;
    for (int n = 0; n < TT; n++) {
        float v = sc[n] + endT[n];
        if (v > best) { best = v; last = n; }
    }

    out[b * SS + SS - 1] = (float)last;
    int cur = last;
    for (int t = SS - 2; t >= 0; t--) {
        cur = hist[(size_t)t * TT + cur];
        out[b * SS + t] = (float)cur;
    }
}

// =============================================================================
// Host (verified input mapper)
// =============================================================================
extern "C" void kernel_launch(void* const* d_in, const int* in_sizes, int n_in,
                              void* d_out, int out_size) {
    const long long SZ_X = (long long)BB * SS * DD;
    const long long SZ_MASK = (long long)BB * SS;
    const long long SZ_WIH = (long long)G4 * DD;
    const long long SZ_WHH = (long long)G4 * HH;
    const long long SZ_B4 = G4;
    const long long SZ_WOUT = (long long)TT * H2;
    const long long SZ_T21 = TT;
    const long long SZ_TR = (long long)TT * TT;

    int ix = -1, imask = -1, iwout = -1, itr = -1;
    int wih[2] = {-1, -1}, whh[2] = {-1, -1}, b4[2] = {-1, -1};
    int t21[3] = {-1, -1, -1};
    int nwih = 0, nwhh = 0, nb4 = 0, nt21 = 0;

    for (int scale_pass = 0; scale_pass < 2 && ix < 0; scale_pass++) {
        const long long mul = scale_pass ? 4 : 1;
        ix = imask = iwout = itr = -1;
        nwih = nwhh = nb4 = nt21 = 0;
        for (int i = 0; i < n_in; i++) {
            long long sz = (long long)in_sizes[i];
            if      (sz == SZ_X * mul)    ix = i;
            else if (sz == SZ_MASK * mul) imask = i;
            else if (sz == SZ_WOUT * mul) iwout = i;
            else if (sz == SZ_TR * mul)   itr = i;
            else if (sz == SZ_WIH * mul && nwih < 2) wih[nwih++] = i;
            else if (sz == SZ_WHH * mul && nwhh < 2) whh[nwhh++] = i;
            else if (sz == SZ_B4 * mul && nb4 < 2)   b4[nb4++] = i;
            else if (sz == SZ_T21 * mul && nt21 < 3) t21[nt21++] = i;
        }
    }

    const bool alpha = (ix == n_in - 1);
    const int iWihf = alpha ? wih[1] : wih[0];
    const int iWihb = alpha ? wih[0] : wih[1];
    const int iWhhf = alpha ? whh[1] : whh[0];
    const int iWhhb = alpha ? whh[0] : whh[1];
    const int ibf   = alpha ? b4[1] : b4[0];
    const int ibb   = alpha ? b4[0] : b4[1];
    const int ibout = t21[0];
    const int ist   = alpha ? t21[2] : t21[1];
    const int ien   = alpha ? t21[1] : t21[2];

    const float* x      = (const float*)d_in[ix];
    const int*   mask   = (const int*)  d_in[imask];
    const float* Wih_f  = (const float*)d_in[iWihf];
    const float* Whh_f  = (const float*)d_in[iWhhf];
    const float* b_f    = (const float*)d_in[ibf];
    const float* Wih_b  = (const float*)d_in[iWihb];
    const float* Whh_b  = (const float*)d_in[iWhhb];
    const float* b_b    = (const float*)d_in[ibb];
    const float* W_out  = (const float*)d_in[iwout];
    const float* b_out  = (const float*)d_in[ibout];
    const float* trans  = (const float*)d_in[itr];
    const float* startT = (const float*)d_in[ist];
    const float* endT   = (const float*)d_in[ien];
    float* out = (float*)d_out;

    cudaFuncSetAttribute(k_rec, cudaFuncAttributeMaxDynamicSharedMemorySize,
                         SMEM_REC_BYTES);

    // 1) input projections (float4 128x128 GEMM)               (1 node)
    k_pre2<<<dim3(G4 / 128, 256, 2), 256>>>(x, Wih_f, b_f, Wih_b, b_b);
    // 2) recurrence: persistent v3, transpose-free staging     (1 node)
    k_rec<<<2 * NBLK_DIR, 512, SMEM_REC_BYTES>>>(Whh_f, Whh_b);
    // 3) emissions                                             (1 node)
    k_emisg<<<dim3(1, SS), 256>>>(W_out, b_out);
    // 4) viterbi (float output)                                (1 node)
    k_vit_naive<<<2, 32>>>(mask, trans, startT, endT, out);
    // total 4 graph nodes.
}